// round 2
// baseline (speedup 1.0000x reference)
#include <cuda_runtime.h>
#include <math.h>

// ---------------------------------------------------------------------------
// UncertaintyWeightedLoss: two segmented softmax cross-entropies over flat
// logits (T = 8.39M each), plus masked note-position MSE, combined with
// uncertainty weights. HBM-bound: 64 MiB compulsory reads -> ~10us floor.
//
// Pipeline (graph-capturable, allocation-free):
//   1. scan_kernel   <<<2, 512>>>   : exclusive prefix sum of counts -> offsets
//   2. seg_ce_kernel <<<2B, 128>>>  : one CTA per (task, segment); single read
//                                     of segment into registers; block max,
//                                     block sum-exp, argmax; per-segment
//                                     partial to __device__ scratch
//   3. finalize_kernel <<<1,1024>>> : deterministic reduce + combination
//
// NOTE: gt_valid is a bool array delivered as int32 (harness dtype set is
// f32/i32/bf16) -> read as const int*.
// ---------------------------------------------------------------------------

#define MAXB 16384

__device__ int           g_off[2][MAXB];        // segment offsets (sys, bar)
__device__ float         g_ce_part[2 * MAXB];   // per-segment CE (0 if invalid)
__device__ unsigned char g_flags[2 * MAXB];     // bit0 = valid, bit1 = correct

// ---------------------------------------------------------------------------
// Exclusive prefix scan of counts. blockIdx.x: 0 = sys, 1 = bar.
// ---------------------------------------------------------------------------
__global__ void scan_kernel(const int* __restrict__ sys_counts,
                            const int* __restrict__ bar_counts, int Bn) {
    __shared__ int s[512];
    const int* counts = (blockIdx.x == 0) ? sys_counts : bar_counts;
    int* offs = g_off[blockIdx.x];
    int t = threadIdx.x;
    int CH = (Bn + 511) >> 9;
    int base = t * CH;

    int sum = 0;
    for (int i = 0; i < CH; ++i) {
        int idx = base + i;
        if (idx < Bn) sum += counts[idx];
    }
    s[t] = sum;
    __syncthreads();
    for (int d = 1; d < 512; d <<= 1) {
        int v = (t >= d) ? s[t - d] : 0;
        __syncthreads();
        s[t] += v;
        __syncthreads();
    }
    int run = (t == 0) ? 0 : s[t - 1];   // exclusive prefix of this chunk
    for (int i = 0; i < CH; ++i) {
        int idx = base + i;
        if (idx < Bn) { offs[idx] = run; run += counts[idx]; }
    }
}

// ---------------------------------------------------------------------------
// Block reductions for 128 threads (4 warps)
// ---------------------------------------------------------------------------
__device__ __forceinline__ float blk_max128(float v, float* s4) {
    #pragma unroll
    for (int o = 16; o; o >>= 1) v = fmaxf(v, __shfl_xor_sync(0xffffffffu, v, o));
    if ((threadIdx.x & 31) == 0) s4[threadIdx.x >> 5] = v;
    __syncthreads();
    return fmaxf(fmaxf(s4[0], s4[1]), fmaxf(s4[2], s4[3]));
}
__device__ __forceinline__ float blk_sum128(float v, float* s4) {
    #pragma unroll
    for (int o = 16; o; o >>= 1) v += __shfl_xor_sync(0xffffffffu, v, o);
    if ((threadIdx.x & 31) == 0) s4[threadIdx.x >> 5] = v;
    __syncthreads();
    return (s4[0] + s4[1]) + (s4[2] + s4[3]);
}
__device__ __forceinline__ int blk_min128(int v, int* s4) {
    #pragma unroll
    for (int o = 16; o; o >>= 1) v = min(v, __shfl_xor_sync(0xffffffffu, v, o));
    if ((threadIdx.x & 31) == 0) s4[threadIdx.x >> 5] = v;
    __syncthreads();
    return min(min(s4[0], s4[1]), min(s4[2], s4[3]));
}

// ---------------------------------------------------------------------------
// One CTA per (task, segment). blockIdx.x in [0, 2B): [0,B) = sys, [B,2B) = bar
// ---------------------------------------------------------------------------
__global__ __launch_bounds__(128) void seg_ce_kernel(
    const float* __restrict__ sys_logits, const float* __restrict__ bar_logits,
    const int* __restrict__ sys_counts,   const int* __restrict__ bar_counts,
    const int* __restrict__ gt_sys,       const int* __restrict__ gt_bar,
    const int* __restrict__ valid, int Bn) {

    __shared__ float smax[4];
    __shared__ float ssum[4];
    __shared__ int   sarg[4];

    int gb = blockIdx.x;
    int task = (gb >= Bn) ? 1 : 0;
    int b = gb - task * Bn;

    const float* logits = task ? bar_logits : sys_logits;
    const int*   counts = task ? bar_counts : sys_counts;
    const int*   gt     = task ? gt_bar     : gt_sys;

    int cnt = counts[b];
    int off = g_off[task][b];
    int t = threadIdx.x;

    // Single-pass load into registers (covers cnt <= 1024; beyond that the
    // fallback re-read hits L1).
    float x[8];
    float mymax = __int_as_float(0xff800000);   // -inf
    int n = 0;
    for (int i = t; i < cnt; i += 128) {
        float v = logits[off + i];
        if (n < 8) x[n] = v;
        ++n;
        mymax = fmaxf(mymax, v);
    }
    float m = blk_max128(mymax, smax);

    float mysum = 0.0f;
    int myarg = 0x7fffffff;
    int k = 0;
    for (int i = t; i < cnt; i += 128) {
        float v = (k < 8) ? x[k] : logits[off + i];
        ++k;
        mysum += __expf(v - m);
        if (v == m) myarg = min(myarg, i);   // first occurrence of max
    }
    float Z = blk_sum128(mysum, ssum);
    int arg = blk_min128(myarg, sarg);

    if (t == 0) {
        int g = gt[b];
        bool vmask = (cnt > 0) && (g >= 0) && (g < cnt) && (valid[b] != 0);
        float ce = 0.0f;
        unsigned char fl = 0;
        if (vmask) {
            float lse = logf(Z) + m;
            ce = lse - logits[off + g];
            fl = 1 | ((arg == g) ? 2 : 0);
        }
        g_ce_part[gb] = ce;
        g_flags[gb] = fl;
    }
}

// ---------------------------------------------------------------------------
// Finalize: deterministic reduction of partials + note MSE + combination.
// ---------------------------------------------------------------------------
__device__ __forceinline__ double blk_sum1024(double v, double* sbuf) {
    int t = threadIdx.x;
    sbuf[t] = v;
    __syncthreads();
    #pragma unroll
    for (int s = 512; s > 0; s >>= 1) {
        if (t < s) sbuf[t] += sbuf[t + s];
        __syncthreads();
    }
    double r = sbuf[0];
    __syncthreads();
    return r;
}

__global__ void finalize_kernel(const float* __restrict__ notep,
                                const float* __restrict__ gtnote,
                                const int* __restrict__ valid,
                                const float* __restrict__ lv_sys,
                                const float* __restrict__ lv_bar,
                                const float* __restrict__ lv_note,
                                int Bn, float* __restrict__ out) {
    __shared__ double sbuf[1024];
    int t = threadIdx.x;

    double ce_s = 0, nv_s = 0, co_s = 0;
    double ce_b = 0, nv_b = 0, co_b = 0;
    double sq = 0, ns = 0;

    for (int b = t; b < Bn; b += 1024) {
        ce_s += (double)g_ce_part[b];
        int f = g_flags[b];
        nv_s += (double)(f & 1);
        co_s += (double)((f >> 1) & 1);

        ce_b += (double)g_ce_part[Bn + b];
        int f2 = g_flags[Bn + b];
        nv_b += (double)(f2 & 1);
        co_b += (double)((f2 >> 1) & 1);

        if (valid[b] != 0) {
            double d = (double)notep[b] - (double)gtnote[b];
            sq += d * d;
            ns += 1.0;
        }
    }

    ce_s = blk_sum1024(ce_s, sbuf);
    nv_s = blk_sum1024(nv_s, sbuf);
    co_s = blk_sum1024(co_s, sbuf);
    ce_b = blk_sum1024(ce_b, sbuf);
    nv_b = blk_sum1024(nv_b, sbuf);
    co_b = blk_sum1024(co_b, sbuf);
    sq   = blk_sum1024(sq,   sbuf);
    ns   = blk_sum1024(ns,   sbuf);

    if (t == 0) {
        double sys_loss  = ce_s / fmax(nv_s, 1.0);
        double bar_loss  = ce_b / fmax(nv_b, 1.0);
        double note_loss = (ns > 0.0) ? sq / fmax(ns, 1.0) : 0.0;

        float lvs = lv_sys[0], lvb = lv_bar[0], lvn = lv_note[0];
        float ps = expf(-lvs), pb = expf(-lvb), pn = expf(-lvn);

        double loss = 0.5 * (double)ps * sys_loss + 0.5 * (double)lvs
                    + 0.5 * (double)pb * bar_loss + 0.5 * (double)lvb
                    + 0.5 * (double)pn * note_loss + 0.5 * (double)lvn;

        out[0] = (float)loss;
        out[1] = (float)sys_loss;
        out[2] = (float)bar_loss;
        out[3] = (float)note_loss;
        out[4] = (float)(co_s / fmax(nv_s, 1.0));
        out[5] = (float)(co_b / fmax(nv_b, 1.0));
        out[6] = ps;
        out[7] = pb;
        out[8] = pn;
    }
}

// ---------------------------------------------------------------------------
// Input order: sys_logits, sys_counts, bar_logits, bar_counts, note_positions,
// gt_system_idx, gt_bar_in_sys, gt_note_position, gt_valid,
// log_var_sys, log_var_bar, log_var_note
// ---------------------------------------------------------------------------
extern "C" void kernel_launch(void* const* d_in, const int* in_sizes, int n_in,
                              void* d_out, int out_size) {
    const float* sys_logits = (const float*)d_in[0];
    const int*   sys_counts = (const int*)d_in[1];
    const float* bar_logits = (const float*)d_in[2];
    const int*   bar_counts = (const int*)d_in[3];
    const float* notep      = (const float*)d_in[4];
    const int*   gt_sys     = (const int*)d_in[5];
    const int*   gt_bar     = (const int*)d_in[6];
    const float* gtnote     = (const float*)d_in[7];
    const int*   valid      = (const int*)d_in[8];
    const float* lvs        = (const float*)d_in[9];
    const float* lvb        = (const float*)d_in[10];
    const float* lvn        = (const float*)d_in[11];

    int Bn = in_sizes[1];
    if (Bn > MAXB) Bn = MAXB;   // scratch capacity guard

    scan_kernel<<<2, 512>>>(sys_counts, bar_counts, Bn);
    seg_ce_kernel<<<2 * Bn, 128>>>(sys_logits, bar_logits, sys_counts,
                                   bar_counts, gt_sys, gt_bar, valid, Bn);
    finalize_kernel<<<1, 1024>>>(notep, gtnote, valid, lvs, lvb, lvn, Bn,
                                 (float*)d_out);
}

// round 3
// speedup vs baseline: 1.2501x; 1.2501x over previous
#include <cuda_runtime.h>
#include <math.h>

// ---------------------------------------------------------------------------
// UncertaintyWeightedLoss: two segmented softmax-CE over flat logits
// (2 x 33.5 MiB f32) + masked note MSE + uncertainty combination.
// DRAM-bound: ~64 MiB compulsory reads -> ~11us floor on GB300.
//
//   1. scan_kernel   <<<2, 1024>>> : shuffle-scan of counts -> offsets (~4us)
//   2. seg_ce_kernel <<<ceil(2B/8), 256>>> : ONE WARP per (task, segment);
//        whole segment (cnt<=544) lives in 17 registers/lane, loaded in one
//        fully-unrolled coalesced batch (MLP=17, no local memory, no smem,
//        no __syncthreads). Warp shfl reductions for max / sum-exp / argmax.
//   3. finalize_kernel <<<1, 1024>>> : deterministic fp64 reduce + combine.
// ---------------------------------------------------------------------------

#define MAXB 16384
#define KMAX 17            // supports cnt <= 544 in the register fast path

__device__ int           g_off[2][MAXB];
__device__ float         g_ce_part[2 * MAXB];
__device__ unsigned char g_flags[2 * MAXB];    // bit0 valid, bit1 correct

// ---------------------------------------------------------------------------
// Exclusive prefix scan of counts (1024 threads, 16 counts each, 2 barriers).
// ---------------------------------------------------------------------------
__global__ __launch_bounds__(1024) void scan_kernel(
    const int* __restrict__ sys_counts, const int* __restrict__ bar_counts,
    int Bn) {
    __shared__ int wtot[32];
    const int* counts = (blockIdx.x == 0) ? sys_counts : bar_counts;
    int* offs = g_off[blockIdx.x];
    int t = threadIdx.x, lane = t & 31, wid = t >> 5;
    int CH = (Bn + 1023) >> 10;          // <= 16 given Bn <= MAXB
    int base = t * CH;

    int c[16];
    int sum = 0;
    #pragma unroll
    for (int k = 0; k < 16; ++k) {
        int idx = base + k;
        int v = (k < CH && idx < Bn) ? counts[idx] : 0;
        c[k] = v;
        sum += v;
    }
    // warp inclusive scan of per-thread sums
    int incl = sum;
    #pragma unroll
    for (int o = 1; o < 32; o <<= 1) {
        int v = __shfl_up_sync(0xffffffffu, incl, o);
        if (lane >= o) incl += v;
    }
    if (lane == 31) wtot[wid] = incl;
    __syncthreads();
    if (wid == 0) {
        int v = wtot[lane];
        #pragma unroll
        for (int o = 1; o < 32; o <<= 1) {
            int u = __shfl_up_sync(0xffffffffu, v, o);
            if (lane >= o) v += u;
        }
        wtot[lane] = v;
    }
    __syncthreads();
    int wbase = (wid == 0) ? 0 : wtot[wid - 1];
    int run = wbase + incl - sum;        // exclusive prefix for this chunk
    #pragma unroll
    for (int k = 0; k < 16; ++k) {
        int idx = base + k;
        if (k < CH && idx < Bn) { offs[idx] = run; run += c[k]; }
    }
}

// ---------------------------------------------------------------------------
// Warp reductions
// ---------------------------------------------------------------------------
__device__ __forceinline__ float wmax(float v) {
    #pragma unroll
    for (int o = 16; o; o >>= 1) v = fmaxf(v, __shfl_xor_sync(0xffffffffu, v, o));
    return v;
}
__device__ __forceinline__ float wsum(float v) {
    #pragma unroll
    for (int o = 16; o; o >>= 1) v += __shfl_xor_sync(0xffffffffu, v, o);
    return v;
}
__device__ __forceinline__ int wmin(int v) {
    #pragma unroll
    for (int o = 16; o; o >>= 1) v = min(v, __shfl_xor_sync(0xffffffffu, v, o));
    return v;
}

// ---------------------------------------------------------------------------
// One WARP per (task, segment). 256 threads = 8 warps per CTA.
// ---------------------------------------------------------------------------
__global__ __launch_bounds__(256) void seg_ce_kernel(
    const float* __restrict__ sys_logits, const float* __restrict__ bar_logits,
    const int* __restrict__ sys_counts,   const int* __restrict__ bar_counts,
    const int* __restrict__ gt_sys,       const int* __restrict__ gt_bar,
    const int* __restrict__ valid, int Bn) {

    int warp = (blockIdx.x << 3) | (threadIdx.x >> 5);
    if (warp >= 2 * Bn) return;
    int lane = threadIdx.x & 31;

    int task = (warp >= Bn) ? 1 : 0;
    int b = warp - task * Bn;

    const float* logits = task ? bar_logits : sys_logits;
    int cnt = (task ? bar_counts : sys_counts)[b];
    int off = g_off[task][b];

    const float NEGINF = __int_as_float(0xff800000);
    float m, Z;
    int arg;

    if (cnt <= 32 * KMAX) {
        // ---- register fast path: whole segment in KMAX regs/lane ----
        float x[KMAX];
        #pragma unroll
        for (int k = 0; k < KMAX; ++k) {
            int i = lane + (k << 5);
            x[k] = (i < cnt) ? logits[off + i] : NEGINF;
        }
        float mymax = x[0];
        #pragma unroll
        for (int k = 1; k < KMAX; ++k) mymax = fmaxf(mymax, x[k]);
        m = wmax(mymax);

        float s = 0.0f;
        int myarg = 0x7fffffff;
        #pragma unroll
        for (int k = 0; k < KMAX; ++k) {
            s += __expf(x[k] - m);                 // exp(-inf) = 0 for padding
            if (x[k] == m) myarg = min(myarg, lane + (k << 5));
        }
        Z = wsum(s);
        arg = wmin(myarg);
    } else {
        // ---- generic two-pass fallback (not hit for this shape) ----
        float mymax = NEGINF;
        for (int i = lane; i < cnt; i += 32)
            mymax = fmaxf(mymax, logits[off + i]);
        m = wmax(mymax);
        float s = 0.0f;
        int myarg = 0x7fffffff;
        for (int i = lane; i < cnt; i += 32) {
            float v = logits[off + i];
            s += __expf(v - m);
            if (v == m) myarg = min(myarg, i);
        }
        Z = wsum(s);
        arg = wmin(myarg);
    }

    if (lane == 0) {
        int g = (task ? gt_bar : gt_sys)[b];
        bool vmask = (cnt > 0) && (g >= 0) && (g < cnt) && (valid[b] != 0);
        float ce = 0.0f;
        unsigned char fl = 0;
        if (vmask) {
            float lse = logf(Z) + m;
            ce = lse - logits[off + g];
            fl = 1 | ((arg == g) ? 2 : 0);
        }
        g_ce_part[warp] = ce;
        g_flags[warp] = fl;
    }
}

// ---------------------------------------------------------------------------
// Finalize: deterministic reduction of partials + note MSE + combination.
// ---------------------------------------------------------------------------
__device__ __forceinline__ double blk_sum1024(double v, double* sbuf) {
    int t = threadIdx.x;
    sbuf[t] = v;
    __syncthreads();
    #pragma unroll
    for (int s = 512; s > 0; s >>= 1) {
        if (t < s) sbuf[t] += sbuf[t + s];
        __syncthreads();
    }
    double r = sbuf[0];
    __syncthreads();
    return r;
}

__global__ __launch_bounds__(1024) void finalize_kernel(
    const float* __restrict__ notep, const float* __restrict__ gtnote,
    const int* __restrict__ valid,
    const float* __restrict__ lv_sys, const float* __restrict__ lv_bar,
    const float* __restrict__ lv_note, int Bn, float* __restrict__ out) {
    __shared__ double sbuf[1024];
    int t = threadIdx.x;

    double ce_s = 0, nv_s = 0, co_s = 0;
    double ce_b = 0, nv_b = 0, co_b = 0;
    double sq = 0, ns = 0;

    for (int b = t; b < Bn; b += 1024) {
        ce_s += (double)g_ce_part[b];
        int f = g_flags[b];
        nv_s += (double)(f & 1);
        co_s += (double)((f >> 1) & 1);

        ce_b += (double)g_ce_part[Bn + b];
        int f2 = g_flags[Bn + b];
        nv_b += (double)(f2 & 1);
        co_b += (double)((f2 >> 1) & 1);

        if (valid[b] != 0) {
            double d = (double)notep[b] - (double)gtnote[b];
            sq += d * d;
            ns += 1.0;
        }
    }

    ce_s = blk_sum1024(ce_s, sbuf);
    nv_s = blk_sum1024(nv_s, sbuf);
    co_s = blk_sum1024(co_s, sbuf);
    ce_b = blk_sum1024(ce_b, sbuf);
    nv_b = blk_sum1024(nv_b, sbuf);
    co_b = blk_sum1024(co_b, sbuf);
    sq   = blk_sum1024(sq,   sbuf);
    ns   = blk_sum1024(ns,   sbuf);

    if (t == 0) {
        double sys_loss  = ce_s / fmax(nv_s, 1.0);
        double bar_loss  = ce_b / fmax(nv_b, 1.0);
        double note_loss = (ns > 0.0) ? sq / fmax(ns, 1.0) : 0.0;

        float lvs = lv_sys[0], lvb = lv_bar[0], lvn = lv_note[0];
        float ps = expf(-lvs), pb = expf(-lvb), pn = expf(-lvn);

        double loss = 0.5 * (double)ps * sys_loss + 0.5 * (double)lvs
                    + 0.5 * (double)pb * bar_loss + 0.5 * (double)lvb
                    + 0.5 * (double)pn * note_loss + 0.5 * (double)lvn;

        out[0] = (float)loss;
        out[1] = (float)sys_loss;
        out[2] = (float)bar_loss;
        out[3] = (float)note_loss;
        out[4] = (float)(co_s / fmax(nv_s, 1.0));
        out[5] = (float)(co_b / fmax(nv_b, 1.0));
        out[6] = ps;
        out[7] = pb;
        out[8] = pn;
    }
}

// ---------------------------------------------------------------------------
extern "C" void kernel_launch(void* const* d_in, const int* in_sizes, int n_in,
                              void* d_out, int out_size) {
    const float* sys_logits = (const float*)d_in[0];
    const int*   sys_counts = (const int*)d_in[1];
    const float* bar_logits = (const float*)d_in[2];
    const int*   bar_counts = (const int*)d_in[3];
    const float* notep      = (const float*)d_in[4];
    const int*   gt_sys     = (const int*)d_in[5];
    const int*   gt_bar     = (const int*)d_in[6];
    const float* gtnote     = (const float*)d_in[7];
    const int*   valid      = (const int*)d_in[8];
    const float* lvs        = (const float*)d_in[9];
    const float* lvb        = (const float*)d_in[10];
    const float* lvn        = (const float*)d_in[11];

    int Bn = in_sizes[1];
    if (Bn > MAXB) Bn = MAXB;

    int nwarps = 2 * Bn;
    int nblocks = (nwarps + 7) / 8;

    scan_kernel<<<2, 1024>>>(sys_counts, bar_counts, Bn);
    seg_ce_kernel<<<nblocks, 256>>>(sys_logits, bar_logits, sys_counts,
                                    bar_counts, gt_sys, gt_bar, valid, Bn);
    finalize_kernel<<<1, 1024>>>(notep, gtnote, valid, lvs, lvb, lvn, Bn,
                                 (float*)d_out);
}

// round 4
// speedup vs baseline: 1.5864x; 1.2691x over previous
#include <cuda_runtime.h>
#include <math.h>

// ---------------------------------------------------------------------------
// UncertaintyWeightedLoss — 2-kernel fused pipeline:
//   1. scan_kernel <<<2, 1024>>>: shuffle-scan of counts -> offsets; also
//      resets the completion counter for the fused kernel.
//   2. fused_kernel <<<nce + note_ctas, 256>>>:
//        - CTAs [0, nce): one WARP per (task, segment); whole segment in
//          registers (float4 x5 fast path / scalar x17 fallback), warp-shfl
//          max / sum-exp / argmax; per-segment partial to scratch.
//        - CTAs [nce, nce+note_ctas): per-CTA fp64 partial of note MSE.
//        - last CTA to finish (ticket via atomicAdd) reduces all partials in
//          fp64 and writes the 9 scalar outputs. Deterministic: fixed data,
//          fixed reduction order.
// ---------------------------------------------------------------------------

#define MAXB 16384
#define KMAX 17           // scalar fast path: cnt <= 544
#define K4   5            // float4 fast path: cnt <= 640

__device__ int           g_off[2][MAXB];
__device__ float         g_ce_part[2 * MAXB];
__device__ unsigned char g_flags[2 * MAXB];      // bit0 valid, bit1 correct
__device__ double        g_note_sq[(MAXB + 255) / 256];
__device__ double        g_note_ns[(MAXB + 255) / 256];
__device__ unsigned int  g_done;

// ---------------------------------------------------------------------------
// Exclusive prefix scan of counts (1024 threads, 16 each). blockIdx: 0/1.
// ---------------------------------------------------------------------------
__global__ __launch_bounds__(1024) void scan_kernel(
    const int* __restrict__ sys_counts, const int* __restrict__ bar_counts,
    int Bn) {
    if (blockIdx.x == 0 && threadIdx.x == 0) g_done = 0;   // reset ticket

    __shared__ int wtot[32];
    const int* counts = (blockIdx.x == 0) ? sys_counts : bar_counts;
    int* offs = g_off[blockIdx.x];
    int t = threadIdx.x, lane = t & 31, wid = t >> 5;
    int CH = (Bn + 1023) >> 10;          // <= 16
    int base = t * CH;

    int c[16];
    int sum = 0;
    if (CH == 16 && base + 15 < Bn && ((base & 3) == 0)) {
        const int4* p = (const int4*)(counts + base);
        #pragma unroll
        for (int q = 0; q < 4; ++q) {
            int4 v = p[q];
            c[q * 4 + 0] = v.x; c[q * 4 + 1] = v.y;
            c[q * 4 + 2] = v.z; c[q * 4 + 3] = v.w;
            sum += v.x + v.y + v.z + v.w;
        }
    } else {
        #pragma unroll
        for (int k = 0; k < 16; ++k) {
            int idx = base + k;
            int v = (k < CH && idx < Bn) ? counts[idx] : 0;
            c[k] = v;
            sum += v;
        }
    }
    int incl = sum;
    #pragma unroll
    for (int o = 1; o < 32; o <<= 1) {
        int v = __shfl_up_sync(0xffffffffu, incl, o);
        if (lane >= o) incl += v;
    }
    if (lane == 31) wtot[wid] = incl;
    __syncthreads();
    if (wid == 0) {
        int v = wtot[lane];
        #pragma unroll
        for (int o = 1; o < 32; o <<= 1) {
            int u = __shfl_up_sync(0xffffffffu, v, o);
            if (lane >= o) v += u;
        }
        wtot[lane] = v;
    }
    __syncthreads();
    int wbase = (wid == 0) ? 0 : wtot[wid - 1];
    int run = wbase + incl - sum;
    #pragma unroll
    for (int k = 0; k < 16; ++k) {
        int idx = base + k;
        if (k < CH && idx < Bn) { offs[idx] = run; run += c[k]; }
    }
}

// ---------------------------------------------------------------------------
__device__ __forceinline__ float wmax(float v) {
    #pragma unroll
    for (int o = 16; o; o >>= 1) v = fmaxf(v, __shfl_xor_sync(0xffffffffu, v, o));
    return v;
}
__device__ __forceinline__ float wsum(float v) {
    #pragma unroll
    for (int o = 16; o; o >>= 1) v += __shfl_xor_sync(0xffffffffu, v, o);
    return v;
}
__device__ __forceinline__ int wmin(int v) {
    #pragma unroll
    for (int o = 16; o; o >>= 1) v = min(v, __shfl_xor_sync(0xffffffffu, v, o));
    return v;
}
__device__ __forceinline__ double blk_sum256(double v, double* s) {
    int t = threadIdx.x;
    s[t] = v;
    __syncthreads();
    #pragma unroll
    for (int k = 128; k > 0; k >>= 1) {
        if (t < k) s[t] += s[t + k];
        __syncthreads();
    }
    double r = s[0];
    __syncthreads();
    return r;
}

// ---------------------------------------------------------------------------
__global__ __launch_bounds__(256, 4) void fused_kernel(
    const float* __restrict__ sys_logits, const float* __restrict__ bar_logits,
    const int* __restrict__ sys_counts,   const int* __restrict__ bar_counts,
    const int* __restrict__ gt_sys,       const int* __restrict__ gt_bar,
    const int* __restrict__ valid,
    const float* __restrict__ notep,      const float* __restrict__ gtnote,
    const float* __restrict__ lv_sys,     const float* __restrict__ lv_bar,
    const float* __restrict__ lv_note,
    int Bn, int nce, float* __restrict__ out) {

    __shared__ double sbuf[256];
    __shared__ unsigned int ticket;

    int cta = blockIdx.x;
    int t = threadIdx.x;
    const float NEGINF = __int_as_float(0xff800000);

    if (cta < nce) {
        // ---------------- segment CE: one warp per (task, segment) ---------
        int warp = (cta << 3) | (t >> 5);
        int lane = t & 31;
        if (warp < 2 * Bn) {
            int task = (warp >= Bn) ? 1 : 0;
            int b = warp - task * Bn;
            const float* logits = task ? bar_logits : sys_logits;
            int cnt = (task ? bar_counts : sys_counts)[b];
            int off = g_off[task][b];

            float m, Z;
            int arg;
            if (((off | cnt) & 3) == 0 && cnt <= 128 * K4) {
                // float4 fast path: 5 vec loads/lane, capacity 640
                float4 x[K4];
                const float4* src = (const float4*)(logits + off);
                int cnt4 = cnt >> 2;
                #pragma unroll
                for (int k = 0; k < K4; ++k) {
                    int vi = lane + (k << 5);
                    if (vi < cnt4) x[k] = src[vi];
                    else x[k] = make_float4(NEGINF, NEGINF, NEGINF, NEGINF);
                }
                float mymax = NEGINF;
                #pragma unroll
                for (int k = 0; k < K4; ++k)
                    mymax = fmaxf(fmaxf(fmaxf(mymax, x[k].x), fmaxf(x[k].y, x[k].z)), x[k].w);
                m = wmax(mymax);

                float s = 0.0f;
                int myarg = 0x7fffffff;
                #pragma unroll
                for (int k = 0; k < K4; ++k) {
                    int e = (lane + (k << 5)) << 2;
                    s += __expf(x[k].x - m) + __expf(x[k].y - m)
                       + __expf(x[k].z - m) + __expf(x[k].w - m);
                    if (x[k].x == m) myarg = min(myarg, e + 0);
                    if (x[k].y == m) myarg = min(myarg, e + 1);
                    if (x[k].z == m) myarg = min(myarg, e + 2);
                    if (x[k].w == m) myarg = min(myarg, e + 3);
                }
                Z = wsum(s);
                arg = wmin(myarg);
            } else if (cnt <= 32 * KMAX) {
                float x[KMAX];
                #pragma unroll
                for (int k = 0; k < KMAX; ++k) {
                    int i = lane + (k << 5);
                    x[k] = (i < cnt) ? logits[off + i] : NEGINF;
                }
                float mymax = x[0];
                #pragma unroll
                for (int k = 1; k < KMAX; ++k) mymax = fmaxf(mymax, x[k]);
                m = wmax(mymax);
                float s = 0.0f;
                int myarg = 0x7fffffff;
                #pragma unroll
                for (int k = 0; k < KMAX; ++k) {
                    s += __expf(x[k] - m);
                    if (x[k] == m) myarg = min(myarg, lane + (k << 5));
                }
                Z = wsum(s);
                arg = wmin(myarg);
            } else {
                // generic two-pass fallback
                float mymax = NEGINF;
                for (int i = lane; i < cnt; i += 32)
                    mymax = fmaxf(mymax, logits[off + i]);
                m = wmax(mymax);
                float s = 0.0f;
                int myarg = 0x7fffffff;
                for (int i = lane; i < cnt; i += 32) {
                    float v = logits[off + i];
                    s += __expf(v - m);
                    if (v == m) myarg = min(myarg, i);
                }
                Z = wsum(s);
                arg = wmin(myarg);
            }

            if (lane == 0) {
                int g = (task ? gt_bar : gt_sys)[b];
                bool vmask = (cnt > 0) && (g >= 0) && (g < cnt) && (valid[b] != 0);
                float ce = 0.0f;
                unsigned char fl = 0;
                if (vmask) {
                    ce = logf(Z) + m - logits[off + g];
                    fl = 1 | ((arg == g) ? 2 : 0);
                }
                g_ce_part[warp] = ce;
                g_flags[warp] = fl;
            }
        }
    } else {
        // ---------------- note MSE partial: 256 rows per CTA ---------------
        int nb = cta - nce;
        int i = (nb << 8) + t;
        double sq = 0.0, ns = 0.0;
        if (i < Bn && valid[i] != 0) {
            double d = (double)notep[i] - (double)gtnote[i];
            sq = d * d;
            ns = 1.0;
        }
        sq = blk_sum256(sq, sbuf);
        ns = blk_sum256(ns, sbuf);
        if (t == 0) { g_note_sq[nb] = sq; g_note_ns[nb] = ns; }
    }

    // ---------------- completion ticket + last-CTA finalize -----------------
    __syncthreads();
    __threadfence();
    if (t == 0) ticket = atomicAdd(&g_done, 1);
    __syncthreads();
    if (ticket != gridDim.x - 1) return;

    int note_ctas = gridDim.x - nce;
    double ce_s = 0, nv_s = 0, co_s = 0;
    double ce_b = 0, nv_b = 0, co_b = 0;
    double sq = 0, ns = 0;

    for (int b = t; b < Bn; b += 256) {
        ce_s += (double)g_ce_part[b];
        int f = g_flags[b];
        nv_s += (double)(f & 1);
        co_s += (double)((f >> 1) & 1);

        ce_b += (double)g_ce_part[Bn + b];
        int f2 = g_flags[Bn + b];
        nv_b += (double)(f2 & 1);
        co_b += (double)((f2 >> 1) & 1);
    }
    for (int i = t; i < note_ctas; i += 256) {
        sq += g_note_sq[i];
        ns += g_note_ns[i];
    }

    ce_s = blk_sum256(ce_s, sbuf);
    nv_s = blk_sum256(nv_s, sbuf);
    co_s = blk_sum256(co_s, sbuf);
    ce_b = blk_sum256(ce_b, sbuf);
    nv_b = blk_sum256(nv_b, sbuf);
    co_b = blk_sum256(co_b, sbuf);
    sq   = blk_sum256(sq,   sbuf);
    ns   = blk_sum256(ns,   sbuf);

    if (t == 0) {
        double sys_loss  = ce_s / fmax(nv_s, 1.0);
        double bar_loss  = ce_b / fmax(nv_b, 1.0);
        double note_loss = (ns > 0.0) ? sq / fmax(ns, 1.0) : 0.0;

        float lvs = lv_sys[0], lvb = lv_bar[0], lvn = lv_note[0];
        float ps = expf(-lvs), pb = expf(-lvb), pn = expf(-lvn);

        double loss = 0.5 * (double)ps * sys_loss + 0.5 * (double)lvs
                    + 0.5 * (double)pb * bar_loss + 0.5 * (double)lvb
                    + 0.5 * (double)pn * note_loss + 0.5 * (double)lvn;

        out[0] = (float)loss;
        out[1] = (float)sys_loss;
        out[2] = (float)bar_loss;
        out[3] = (float)note_loss;
        out[4] = (float)(co_s / fmax(nv_s, 1.0));
        out[5] = (float)(co_b / fmax(nv_b, 1.0));
        out[6] = ps;
        out[7] = pb;
        out[8] = pn;
    }
}

// ---------------------------------------------------------------------------
extern "C" void kernel_launch(void* const* d_in, const int* in_sizes, int n_in,
                              void* d_out, int out_size) {
    const float* sys_logits = (const float*)d_in[0];
    const int*   sys_counts = (const int*)d_in[1];
    const float* bar_logits = (const float*)d_in[2];
    const int*   bar_counts = (const int*)d_in[3];
    const float* notep      = (const float*)d_in[4];
    const int*   gt_sys     = (const int*)d_in[5];
    const int*   gt_bar     = (const int*)d_in[6];
    const float* gtnote     = (const float*)d_in[7];
    const int*   valid      = (const int*)d_in[8];
    const float* lvs        = (const float*)d_in[9];
    const float* lvb        = (const float*)d_in[10];
    const float* lvn        = (const float*)d_in[11];

    int Bn = in_sizes[1];
    if (Bn > MAXB) Bn = MAXB;

    int nce = (2 * Bn + 7) / 8;          // warp-per-segment CTAs
    int note_ctas = (Bn + 255) / 256;    // note-MSE partial CTAs

    scan_kernel<<<2, 1024>>>(sys_counts, bar_counts, Bn);
    fused_kernel<<<nce + note_ctas, 256>>>(
        sys_logits, bar_logits, sys_counts, bar_counts, gt_sys, gt_bar, valid,
        notep, gtnote, lvs, lvb, lvn, Bn, nce, (float*)d_out);
}

// round 5
// speedup vs baseline: 2.4904x; 1.5698x over previous
#include <cuda_runtime.h>
#include <math.h>

// ---------------------------------------------------------------------------
// UncertaintyWeightedLoss — single fused kernel:
//   CTA 0,1            : prefix-scan of sys/bar counts -> g_off, release flag
//   CTA [2, 2+NB)      : note-MSE partials (independent of scan)
//   CTA [2+NB, ...)    : one WARP per (task, segment): acquire-spin on scan
//                        flag, whole segment in registers (float4 x5), warp
//                        shfl reductions; ex2.approx-based softmax-CE
//   last CTA (ticket)  : fp64 reduce of all partials, 9 outputs, reset state
// ---------------------------------------------------------------------------

#define MAXB 16384
#define KMAX 17                 // scalar fast path capacity 544
#define K4   5                  // float4 fast path capacity 640
#define NOTE_CHUNK 256
#define L2E 1.4426950408889634f

__device__ int           g_off[2][MAXB];
__device__ float         g_ce_part[2 * MAXB];
__device__ unsigned char g_flags[2 * MAXB];       // bit0 valid, bit1 correct
__device__ double        g_note_sq[(MAXB + NOTE_CHUNK - 1) / NOTE_CHUNK];
__device__ double        g_note_ns[(MAXB + NOTE_CHUNK - 1) / NOTE_CHUNK];
__device__ unsigned int  g_done;                  // completion ticket
__device__ unsigned int  g_scan_done;             // scan release flag

__device__ __forceinline__ float ex2f(float x) {
    float r;
    asm("ex2.approx.f32 %0, %1;" : "=f"(r) : "f"(x));
    return r;
}
__device__ __forceinline__ unsigned int ldacq(const unsigned int* p) {
    unsigned int v;
    asm volatile("ld.acquire.gpu.u32 %0, [%1];" : "=r"(v) : "l"(p) : "memory");
    return v;
}
__device__ __forceinline__ float wmax(float v) {
    #pragma unroll
    for (int o = 16; o; o >>= 1) v = fmaxf(v, __shfl_xor_sync(0xffffffffu, v, o));
    return v;
}
__device__ __forceinline__ float wsum(float v) {
    #pragma unroll
    for (int o = 16; o; o >>= 1) v += __shfl_xor_sync(0xffffffffu, v, o);
    return v;
}
__device__ __forceinline__ int wmin(int v) {
    #pragma unroll
    for (int o = 16; o; o >>= 1) v = min(v, __shfl_xor_sync(0xffffffffu, v, o));
    return v;
}

// in-kernel scan for one task (256 threads)
__device__ void do_scan(const int* __restrict__ counts, int* __restrict__ offs,
                        int Bn, int* wtot) {
    int t = threadIdx.x, lane = t & 31, wid = t >> 5;
    int CH = (Bn + 255) >> 8;
    int base = t * CH;

    int sum = 0;
    for (int k = 0; k < CH; ++k) {
        int idx = base + k;
        if (idx < Bn) sum += counts[idx];
    }
    int incl = sum;
    #pragma unroll
    for (int o = 1; o < 32; o <<= 1) {
        int v = __shfl_up_sync(0xffffffffu, incl, o);
        if (lane >= o) incl += v;
    }
    if (lane == 31) wtot[wid] = incl;
    __syncthreads();
    if (wid == 0 && lane < 8) {
        int v = wtot[lane];
        #pragma unroll
        for (int o = 1; o < 8; o <<= 1) {
            int u = __shfl_up_sync(0x000000ffu, v, o);
            if (lane >= o) v += u;
        }
        wtot[lane] = v;
    }
    __syncthreads();
    int wbase = (wid == 0) ? 0 : wtot[wid - 1];
    int run = wbase + incl - sum;                 // exclusive prefix
    for (int k = 0; k < CH; ++k) {
        int idx = base + k;
        if (idx < Bn) { offs[idx] = run; run += counts[idx]; }
    }
}

__device__ __forceinline__ double blk_sum256(double v, double* s) {
    int t = threadIdx.x;
    s[t] = v;
    __syncthreads();
    #pragma unroll
    for (int k = 128; k > 0; k >>= 1) {
        if (t < k) s[t] += s[t + k];
        __syncthreads();
    }
    double r = s[0];
    __syncthreads();
    return r;
}

__global__ __launch_bounds__(256, 6) void fused_kernel(
    const float* __restrict__ sys_logits, const float* __restrict__ bar_logits,
    const int* __restrict__ sys_counts,   const int* __restrict__ bar_counts,
    const int* __restrict__ gt_sys,       const int* __restrict__ gt_bar,
    const int* __restrict__ valid,
    const float* __restrict__ notep,      const float* __restrict__ gtnote,
    const float* __restrict__ lv_sys,     const float* __restrict__ lv_bar,
    const float* __restrict__ lv_note,
    int Bn, int note_ctas, float* __restrict__ out) {

    __shared__ double sbuf[256];
    __shared__ int    wtot[8];
    __shared__ unsigned int ticket;

    int cta = blockIdx.x;
    int t = threadIdx.x;
    const float NEGINF = __int_as_float(0xff800000);
    int ce_base = 2 + note_ctas;

    if (cta < 2) {
        // ------------- scan (one task per CTA) -------------
        do_scan(cta == 0 ? sys_counts : bar_counts, g_off[cta], Bn, wtot);
        __threadfence();
        __syncthreads();
        if (t == 0) atomicAdd(&g_scan_done, 1u);
    } else if (cta < ce_base) {
        // ------------- note-MSE partial -------------
        int nb = cta - 2;
        int i = nb * NOTE_CHUNK + t;
        double sq = 0.0, ns = 0.0;
        if (i < Bn && valid[i] != 0) {
            double d = (double)notep[i] - (double)gtnote[i];
            sq = d * d;
            ns = 1.0;
        }
        sq = blk_sum256(sq, sbuf);
        ns = blk_sum256(ns, sbuf);
        if (t == 0) { g_note_sq[nb] = sq; g_note_ns[nb] = ns; }
    } else {
        // ------------- segment CE: one warp per (task, segment) -------------
        int warp = ((cta - ce_base) << 3) | (t >> 5);
        int lane = t & 31;
        int tot = 2 * Bn;

        int task = 0, b = 0, cnt = 0, g = 0;
        const float* logits = sys_logits;
        if (warp < tot) {
            task = (warp >= Bn) ? 1 : 0;
            b = warp - task * Bn;
            logits = task ? bar_logits : sys_logits;
            cnt = (task ? bar_counts : sys_counts)[b];     // overlap with spin
            g = (task ? gt_bar : gt_sys)[b];
        }

        if (t == 0) {
            while (ldacq(&g_scan_done) < 2u) __nanosleep(64);
        }
        __syncthreads();

        if (warp < tot) {
            int off = __ldcg(&g_off[task][b]);

            float m, Z;
            int arg;
            if (((off | cnt) & 3) == 0 && cnt <= 128 * K4) {
                float4 x[K4];
                const float4* src = (const float4*)(logits + off);
                int cnt4 = cnt >> 2;
                #pragma unroll
                for (int k = 0; k < K4; ++k) {
                    int vi = lane + (k << 5);
                    if (vi < cnt4) x[k] = src[vi];
                    else x[k] = make_float4(NEGINF, NEGINF, NEGINF, NEGINF);
                }
                float mymax = NEGINF;
                #pragma unroll
                for (int k = 0; k < K4; ++k)
                    mymax = fmaxf(fmaxf(fmaxf(mymax, x[k].x),
                                        fmaxf(x[k].y, x[k].z)), x[k].w);
                m = wmax(mymax);

                float a = m * L2E;                 // exp(v-m) = ex2(v*L2E - a)
                float s = 0.0f;
                int myarg = 0x7fffffff;
                #pragma unroll
                for (int k = 0; k < K4; ++k) {
                    int e = (lane + (k << 5)) << 2;
                    s += ex2f(fmaf(x[k].x, L2E, -a))
                       + ex2f(fmaf(x[k].y, L2E, -a))
                       + ex2f(fmaf(x[k].z, L2E, -a))
                       + ex2f(fmaf(x[k].w, L2E, -a));
                    if (x[k].x == m) myarg = min(myarg, e + 0);
                    if (x[k].y == m) myarg = min(myarg, e + 1);
                    if (x[k].z == m) myarg = min(myarg, e + 2);
                    if (x[k].w == m) myarg = min(myarg, e + 3);
                }
                Z = wsum(s);
                arg = wmin(myarg);
            } else if (cnt <= 32 * KMAX) {
                float x[KMAX];
                #pragma unroll
                for (int k = 0; k < KMAX; ++k) {
                    int i = lane + (k << 5);
                    x[k] = (i < cnt) ? logits[off + i] : NEGINF;
                }
                float mymax = x[0];
                #pragma unroll
                for (int k = 1; k < KMAX; ++k) mymax = fmaxf(mymax, x[k]);
                m = wmax(mymax);
                float a = m * L2E;
                float s = 0.0f;
                int myarg = 0x7fffffff;
                #pragma unroll
                for (int k = 0; k < KMAX; ++k) {
                    s += ex2f(fmaf(x[k], L2E, -a));
                    if (x[k] == m) myarg = min(myarg, lane + (k << 5));
                }
                Z = wsum(s);
                arg = wmin(myarg);
            } else {
                float mymax = NEGINF;
                for (int i = lane; i < cnt; i += 32)
                    mymax = fmaxf(mymax, logits[off + i]);
                m = wmax(mymax);
                float a = m * L2E;
                float s = 0.0f;
                int myarg = 0x7fffffff;
                for (int i = lane; i < cnt; i += 32) {
                    float v = logits[off + i];
                    s += ex2f(fmaf(v, L2E, -a));
                    if (v == m) myarg = min(myarg, i);
                }
                Z = wsum(s);
                arg = wmin(myarg);
            }

            if (lane == 0) {
                bool vmask = (cnt > 0) && (g >= 0) && (g < cnt) && (valid[b] != 0);
                float ce = 0.0f;
                unsigned char fl = 0;
                if (vmask) {
                    ce = logf(Z) + m - logits[off + g];
                    fl = 1 | ((arg == g) ? 2 : 0);
                }
                g_ce_part[warp] = ce;
                g_flags[warp] = fl;
            }
        }
    }

    // ------------- completion ticket + last-CTA finalize -------------
    __syncthreads();
    __threadfence();
    if (t == 0) ticket = atomicAdd(&g_done, 1u);
    __syncthreads();
    if (ticket != gridDim.x - 1) return;

    if (t == 0) { g_done = 0; g_scan_done = 0; }    // reset for next replay

    double ce_s = 0, ce_b = 0, sq = 0, ns = 0;
    int nv_s = 0, co_s = 0, nv_b = 0, co_b = 0;

    if ((Bn & 3) == 0) {
        int q = Bn >> 2;
        const float4* cp = (const float4*)g_ce_part;
        const unsigned int* fp = (const unsigned int*)g_flags;
        for (int i = t; i < q; i += 256) {
            float4 v = __ldcg(cp + i);
            ce_s += (double)((v.x + v.y) + (v.z + v.w));
            unsigned int w = __ldcg(fp + i);
            nv_s += __popc(w & 0x01010101u);
            co_s += __popc(w & 0x02020202u);
        }
        for (int i = t; i < q; i += 256) {
            float4 v = __ldcg(cp + q + i);
            ce_b += (double)((v.x + v.y) + (v.z + v.w));
            unsigned int w = __ldcg(fp + q + i);
            nv_b += __popc(w & 0x01010101u);
            co_b += __popc(w & 0x02020202u);
        }
    } else {
        for (int b = t; b < Bn; b += 256) {
            ce_s += (double)__ldcg(&g_ce_part[b]);
            int f = g_flags[b];
            nv_s += f & 1; co_s += (f >> 1) & 1;
            ce_b += (double)__ldcg(&g_ce_part[Bn + b]);
            int f2 = g_flags[Bn + b];
            nv_b += f2 & 1; co_b += (f2 >> 1) & 1;
        }
    }
    for (int i = t; i < note_ctas; i += 256) {
        sq += __ldcg(&g_note_sq[i]);
        ns += __ldcg(&g_note_ns[i]);
    }

    ce_s = blk_sum256(ce_s, sbuf);
    double dnv_s = blk_sum256((double)nv_s, sbuf);
    double dco_s = blk_sum256((double)co_s, sbuf);
    ce_b = blk_sum256(ce_b, sbuf);
    double dnv_b = blk_sum256((double)nv_b, sbuf);
    double dco_b = blk_sum256((double)co_b, sbuf);
    sq = blk_sum256(sq, sbuf);
    ns = blk_sum256(ns, sbuf);

    if (t == 0) {
        double sys_loss  = ce_s / fmax(dnv_s, 1.0);
        double bar_loss  = ce_b / fmax(dnv_b, 1.0);
        double note_loss = (ns > 0.0) ? sq / fmax(ns, 1.0) : 0.0;

        float lvs = lv_sys[0], lvb = lv_bar[0], lvn = lv_note[0];
        float ps = expf(-lvs), pb = expf(-lvb), pn = expf(-lvn);

        double loss = 0.5 * (double)ps * sys_loss + 0.5 * (double)lvs
                    + 0.5 * (double)pb * bar_loss + 0.5 * (double)lvb
                    + 0.5 * (double)pn * note_loss + 0.5 * (double)lvn;

        out[0] = (float)loss;
        out[1] = (float)sys_loss;
        out[2] = (float)bar_loss;
        out[3] = (float)note_loss;
        out[4] = (float)(dco_s / fmax(dnv_s, 1.0));
        out[5] = (float)(dco_b / fmax(dnv_b, 1.0));
        out[6] = ps;
        out[7] = pb;
        out[8] = pn;
    }
}

// ---------------------------------------------------------------------------
extern "C" void kernel_launch(void* const* d_in, const int* in_sizes, int n_in,
                              void* d_out, int out_size) {
    const float* sys_logits = (const float*)d_in[0];
    const int*   sys_counts = (const int*)d_in[1];
    const float* bar_logits = (const float*)d_in[2];
    const int*   bar_counts = (const int*)d_in[3];
    const float* notep      = (const float*)d_in[4];
    const int*   gt_sys     = (const int*)d_in[5];
    const int*   gt_bar     = (const int*)d_in[6];
    const float* gtnote     = (const float*)d_in[7];
    const int*   valid      = (const int*)d_in[8];
    const float* lvs        = (const float*)d_in[9];
    const float* lvb        = (const float*)d_in[10];
    const float* lvn        = (const float*)d_in[11];

    int Bn = in_sizes[1];
    if (Bn > MAXB) Bn = MAXB;

    int nce = (2 * Bn + 7) / 8;                        // warp-per-segment CTAs
    int note_ctas = (Bn + NOTE_CHUNK - 1) / NOTE_CHUNK;
    int grid = 2 + note_ctas + nce;

    fused_kernel<<<grid, 256>>>(
        sys_logits, bar_logits, sys_counts, bar_counts, gt_sys, gt_bar, valid,
        notep, gtnote, lvs, lvb, lvn, Bn, note_ctas, (float*)d_out);
}

// round 6
// speedup vs baseline: 3.7877x; 1.5209x over previous
#include <cuda_runtime.h>
#include <math.h>

// ---------------------------------------------------------------------------
// UncertaintyWeightedLoss — single persistent fused kernel (one wave):
//   CTA 0,1         : int4-unrolled prefix scan of counts -> g_off, release
//   CTA [2,2+NB)    : note-MSE partials
//   CTA [2+NB,...)  : PERSISTENT CE CTAs, 8 warps each; every warp processes
//                     ~tot/warps segments with a 2-deep software pipeline
//                     (next segment's float4 loads + meta prefetched 2 ahead
//                     overlap current segment's compute). Per-CTA partials.
//   last CTA ticket : reduce ~NCE+NB small partials, 9 outputs, reset state.
// ---------------------------------------------------------------------------

#define MAXB 16384
#define K4   5                   // float4 regs/lane -> capacity 640 elems
#define NOTE_CHUNK 256
#define MAXCTA 1024
#define L2E 1.4426950408889634f

__device__ int           g_off[2][MAXB];
__device__ double        g_part_ce_s[MAXCTA];
__device__ double        g_part_ce_b[MAXCTA];
__device__ unsigned int  g_part_cnt[MAXCTA];   // nv_s | co_s<<8 | nv_b<<16 | co_b<<24
__device__ double        g_note_sq[(MAXB + NOTE_CHUNK - 1) / NOTE_CHUNK];
__device__ double        g_note_ns[(MAXB + NOTE_CHUNK - 1) / NOTE_CHUNK];
__device__ unsigned int  g_done;
__device__ unsigned int  g_scan_done;

__device__ __forceinline__ float ex2f(float x) {
    float r;
    asm("ex2.approx.f32 %0, %1;" : "=f"(r) : "f"(x));
    return r;
}
__device__ __forceinline__ unsigned int ldacq(const unsigned int* p) {
    unsigned int v;
    asm volatile("ld.acquire.gpu.u32 %0, [%1];" : "=r"(v) : "l"(p) : "memory");
    return v;
}
__device__ __forceinline__ float wmax(float v) {
    #pragma unroll
    for (int o = 16; o; o >>= 1) v = fmaxf(v, __shfl_xor_sync(0xffffffffu, v, o));
    return v;
}
__device__ __forceinline__ float wsum(float v) {
    #pragma unroll
    for (int o = 16; o; o >>= 1) v += __shfl_xor_sync(0xffffffffu, v, o);
    return v;
}
__device__ __forceinline__ int wmin(int v) {
    #pragma unroll
    for (int o = 16; o; o >>= 1) v = min(v, __shfl_xor_sync(0xffffffffu, v, o));
    return v;
}
__device__ __forceinline__ double blk_sum256(double v, double* s) {
    int t = threadIdx.x;
    s[t] = v;
    __syncthreads();
    #pragma unroll
    for (int k = 128; k > 0; k >>= 1) {
        if (t < k) s[t] += s[t + k];
        __syncthreads();
    }
    double r = s[0];
    __syncthreads();
    return r;
}

// prefix scan for one task, 256 threads, int4-vectorized (MLP 4)
__device__ void do_scan(const int* __restrict__ counts, int* __restrict__ offs,
                        int Bn, int* wtot) {
    int t = threadIdx.x, lane = t & 31, wid = t >> 5;
    int CH = (Bn + 255) >> 8;
    int base = t * CH;
    bool vec = ((CH & 3) == 0) && (base + CH <= Bn);

    int sum = 0;
    if (vec) {
        const int4* p = (const int4*)(counts + base);
        int q4 = CH >> 2;
        #pragma unroll 4
        for (int q = 0; q < q4; ++q) {
            int4 v = p[q];
            sum += (v.x + v.y) + (v.z + v.w);
        }
    } else {
        for (int k = 0; k < CH; ++k) {
            int idx = base + k;
            if (idx < Bn) sum += counts[idx];
        }
    }
    int incl = sum;
    #pragma unroll
    for (int o = 1; o < 32; o <<= 1) {
        int v = __shfl_up_sync(0xffffffffu, incl, o);
        if (lane >= o) incl += v;
    }
    if (lane == 31) wtot[wid] = incl;
    __syncthreads();
    if (wid == 0 && lane < 8) {
        int v = wtot[lane];
        #pragma unroll
        for (int o = 1; o < 8; o <<= 1) {
            int u = __shfl_up_sync(0x000000ffu, v, o);
            if (lane >= o) v += u;
        }
        wtot[lane] = v;
    }
    __syncthreads();
    int wbase = (wid == 0) ? 0 : wtot[wid - 1];
    int run = wbase + incl - sum;
    if (vec) {
        const int4* p = (const int4*)(counts + base);
        int4* po = (int4*)(offs + base);
        int q4 = CH >> 2;
        #pragma unroll 4
        for (int q = 0; q < q4; ++q) {
            int4 v = p[q];
            int4 o;
            o.x = run; run += v.x;
            o.y = run; run += v.y;
            o.z = run; run += v.z;
            o.w = run; run += v.w;
            po[q] = o;
        }
    } else {
        for (int k = 0; k < CH; ++k) {
            int idx = base + k;
            if (idx < Bn) { offs[idx] = run; run += counts[idx]; }
        }
    }
}

__global__ __launch_bounds__(256, 3) void fused_kernel(
    const float* __restrict__ sys_logits, const float* __restrict__ bar_logits,
    const int* __restrict__ sys_counts,   const int* __restrict__ bar_counts,
    const int* __restrict__ gt_sys,       const int* __restrict__ gt_bar,
    const int* __restrict__ valid,
    const float* __restrict__ notep,      const float* __restrict__ gtnote,
    const float* __restrict__ lv_sys,     const float* __restrict__ lv_bar,
    const float* __restrict__ lv_note,
    int Bn, int note_ctas, int nce, float* __restrict__ out) {

    __shared__ double sbuf[256];
    __shared__ int    wtot[8];
    __shared__ float  s_ce[2][8];
    __shared__ int    s_nv[2][8], s_co[2][8];
    __shared__ unsigned int ticket;

    int cta = blockIdx.x;
    int t = threadIdx.x;
    const float NEGINF = __int_as_float(0xff800000);
    int ce_base = 2 + note_ctas;

    if (cta < 2) {
        // ---------------- scan ----------------
        do_scan(cta == 0 ? sys_counts : bar_counts, g_off[cta], Bn, wtot);
        __threadfence();
        __syncthreads();
        if (t == 0) atomicAdd(&g_scan_done, 1u);
    } else if (cta < ce_base) {
        // ---------------- note-MSE partial ----------------
        int nb = cta - 2;
        int i = nb * NOTE_CHUNK + t;
        double sq = 0.0, ns = 0.0;
        if (i < Bn && valid[i] != 0) {
            double d = (double)notep[i] - (double)gtnote[i];
            sq = d * d;
            ns = 1.0;
        }
        sq = blk_sum256(sq, sbuf);
        ns = blk_sum256(ns, sbuf);
        if (t == 0) { g_note_sq[nb] = sq; g_note_ns[nb] = ns; }
    } else {
        // ---------------- persistent pipelined CE ----------------
        int lane = t & 31;
        int w = t >> 5;
        int tot = 2 * Bn;
        int stride = nce << 3;
        int gw = ((cta - ce_base) << 3) | w;

        // wait for scan (meta depends on g_off)
        if (t == 0) {
            while (ldacq(&g_scan_done) < 2u) __nanosleep(64);
        }
        __syncthreads();

        float ces = 0.0f, ceb = 0.0f;
        int nvs = 0, cos_ = 0, nvb = 0, cob = 0;

        auto fetchmeta = [&](int s, int& c, int& o, int& g, int& v) {
            int task = (s >= Bn) ? 1 : 0;
            int b = s - task * Bn;
            c = task ? bar_counts[b] : sys_counts[b];
            o = __ldcg(&g_off[task][b]);
            g = task ? gt_bar[b] : gt_sys[b];
            v = valid[b];
        };
        auto loadbuf = [&](float4* x, int s, int c, int o) {
            const float* ptr = (s >= Bn) ? bar_logits : sys_logits;
            if (((o | c) & 3) == 0 && c <= 128 * K4) {
                const float4* src = (const float4*)(ptr + o);
                int c4 = c >> 2;
                #pragma unroll
                for (int k = 0; k < K4; ++k) {
                    int vi = lane + (k << 5);
                    if (vi < c4) x[k] = src[vi];
                    else x[k] = make_float4(NEGINF, NEGINF, NEGINF, NEGINF);
                }
            } else if (c <= 128 * K4) {
                #pragma unroll
                for (int k = 0; k < K4; ++k) {
                    int e = (lane + (k << 5)) << 2;
                    x[k].x = (e + 0 < c) ? ptr[o + e + 0] : NEGINF;
                    x[k].y = (e + 1 < c) ? ptr[o + e + 1] : NEGINF;
                    x[k].z = (e + 2 < c) ? ptr[o + e + 2] : NEGINF;
                    x[k].w = (e + 3 < c) ? ptr[o + e + 3] : NEGINF;
                }
            }
        };
        auto process = [&](float4* x, int s, int c, int o, int g, int vld) {
            int task = (s >= Bn) ? 1 : 0;
            const float* ptr = task ? bar_logits : sys_logits;
            float m, Z, tlogit;
            int arg;
            if (c <= 128 * K4) {
                float mymax = NEGINF;
                #pragma unroll
                for (int k = 0; k < K4; ++k)
                    mymax = fmaxf(fmaxf(fmaxf(mymax, x[k].x),
                                        fmaxf(x[k].y, x[k].z)), x[k].w);
                m = wmax(mymax);
                float a = m * L2E;
                float sm = 0.0f;
                int myarg = 0x7fffffff;
                #pragma unroll
                for (int k = 0; k < K4; ++k) {
                    int e = (lane + (k << 5)) << 2;
                    sm += ex2f(fmaf(x[k].x, L2E, -a))
                        + ex2f(fmaf(x[k].y, L2E, -a))
                        + ex2f(fmaf(x[k].z, L2E, -a))
                        + ex2f(fmaf(x[k].w, L2E, -a));
                    if (x[k].x == m) myarg = min(myarg, e + 0);
                    if (x[k].y == m) myarg = min(myarg, e + 1);
                    if (x[k].z == m) myarg = min(myarg, e + 2);
                    if (x[k].w == m) myarg = min(myarg, e + 3);
                }
                Z = wsum(sm);
                arg = wmin(myarg);
                // extract target logit from registers (uniform g)
                int gi = min(max(g, 0), 128 * K4 - 1);
                int q = gi >> 2, kk = q >> 5, j = gi & 3;
                float4 xx = (kk == 0) ? x[0] : (kk == 1) ? x[1] :
                            (kk == 2) ? x[2] : (kk == 3) ? x[3] : x[4];
                float cand = (j == 0) ? xx.x : (j == 1) ? xx.y :
                             (j == 2) ? xx.z : xx.w;
                tlogit = __shfl_sync(0xffffffffu, cand, q & 31);
            } else {
                // streaming fallback for oversized segments
                float mymax = NEGINF;
                for (int i = lane; i < c; i += 32)
                    mymax = fmaxf(mymax, ptr[o + i]);
                m = wmax(mymax);
                float a = m * L2E;
                float sm = 0.0f;
                int myarg = 0x7fffffff;
                for (int i = lane; i < c; i += 32) {
                    float v = ptr[o + i];
                    sm += ex2f(fmaf(v, L2E, -a));
                    if (v == m) myarg = min(myarg, i);
                }
                Z = wsum(sm);
                arg = wmin(myarg);
                tlogit = (g >= 0 && g < c) ? ptr[o + g] : 0.0f;
            }
            if (lane == 0) {
                bool vmask = (c > 0) && (g >= 0) && (g < c) && (vld != 0);
                if (vmask) {
                    float ce = logf(Z) + m - tlogit;
                    int cor = (arg == g) ? 1 : 0;
                    if (task) { ceb += ce; nvb += 1; cob += cor; }
                    else      { ces += ce; nvs += 1; cos_ += cor; }
                }
            }
        };

        float4 cur[K4], nxt[K4];
        int s0 = gw;
        int c0 = 0, o0 = 0, g0 = 0, v0 = 0;
        int c1 = 0, o1 = 0, g1 = 0, v1 = 0;
        int s1 = s0 + stride;
        if (s0 < tot) {
            fetchmeta(s0, c0, o0, g0, v0);
            loadbuf(cur, s0, c0, o0);
            if (s1 < tot) fetchmeta(s1, c1, o1, g1, v1);
        }
        while (s0 < tot) {
            if (s1 < tot) loadbuf(nxt, s1, c1, o1);
            int s2 = s1 + stride;
            int c2 = 0, o2 = 0, g2 = 0, v2 = 0;
            if (s2 < tot) fetchmeta(s2, c2, o2, g2, v2);
            process(cur, s0, c0, o0, g0, v0);
            #pragma unroll
            for (int k = 0; k < K4; ++k) cur[k] = nxt[k];
            s0 = s1; c0 = c1; o0 = o1; g0 = g1; v0 = v1;
            s1 = s2; c1 = c2; o1 = o2; g1 = g2; v1 = v2;
        }

        // per-CTA reduction of warp accumulators (fixed order -> deterministic)
        if (lane == 0) {
            s_ce[0][w] = ces; s_ce[1][w] = ceb;
            s_nv[0][w] = nvs; s_nv[1][w] = nvb;
            s_co[0][w] = cos_; s_co[1][w] = cob;
        }
        __syncthreads();
        if (t == 0) {
            float tce_s = 0.0f, tce_b = 0.0f;
            int tnv_s = 0, tco_s = 0, tnv_b = 0, tco_b = 0;
            #pragma unroll
            for (int i = 0; i < 8; ++i) {
                tce_s += s_ce[0][i]; tce_b += s_ce[1][i];
                tnv_s += s_nv[0][i]; tnv_b += s_nv[1][i];
                tco_s += s_co[0][i]; tco_b += s_co[1][i];
            }
            int ci = cta - ce_base;
            g_part_ce_s[ci] = (double)tce_s;
            g_part_ce_b[ci] = (double)tce_b;
            g_part_cnt[ci] = (unsigned int)tnv_s | ((unsigned int)tco_s << 8)
                           | ((unsigned int)tnv_b << 16) | ((unsigned int)tco_b << 24);
        }
    }

    // ---------------- ticket + last-CTA finalize ----------------
    __syncthreads();
    __threadfence();
    if (t == 0) ticket = atomicAdd(&g_done, 1u);
    __syncthreads();
    if (ticket != gridDim.x - 1) return;

    if (t == 0) { g_done = 0; g_scan_done = 0; }

    double ce_s = 0, ce_b = 0, sq = 0, ns = 0;
    int nv_s = 0, co_s = 0, nv_b = 0, co_b = 0;

    for (int i = t; i < nce; i += 256) {
        ce_s += __ldcg(&g_part_ce_s[i]);
        ce_b += __ldcg(&g_part_ce_b[i]);
        unsigned int pc = __ldcg(&g_part_cnt[i]);
        nv_s += pc & 0xff;         co_s += (pc >> 8) & 0xff;
        nv_b += (pc >> 16) & 0xff; co_b += (pc >> 24) & 0xff;
    }
    for (int i = t; i < note_ctas; i += 256) {
        sq += __ldcg(&g_note_sq[i]);
        ns += __ldcg(&g_note_ns[i]);
    }

    ce_s = blk_sum256(ce_s, sbuf);
    double dnv_s = blk_sum256((double)nv_s, sbuf);
    double dco_s = blk_sum256((double)co_s, sbuf);
    ce_b = blk_sum256(ce_b, sbuf);
    double dnv_b = blk_sum256((double)nv_b, sbuf);
    double dco_b = blk_sum256((double)co_b, sbuf);
    sq = blk_sum256(sq, sbuf);
    ns = blk_sum256(ns, sbuf);

    if (t == 0) {
        double sys_loss  = ce_s / fmax(dnv_s, 1.0);
        double bar_loss  = ce_b / fmax(dnv_b, 1.0);
        double note_loss = (ns > 0.0) ? sq / fmax(ns, 1.0) : 0.0;

        float lvs = lv_sys[0], lvb = lv_bar[0], lvn = lv_note[0];
        float ps = expf(-lvs), pb = expf(-lvb), pn = expf(-lvn);

        double loss = 0.5 * (double)ps * sys_loss + 0.5 * (double)lvs
                    + 0.5 * (double)pb * bar_loss + 0.5 * (double)lvb
                    + 0.5 * (double)pn * note_loss + 0.5 * (double)lvn;

        out[0] = (float)loss;
        out[1] = (float)sys_loss;
        out[2] = (float)bar_loss;
        out[3] = (float)note_loss;
        out[4] = (float)(dco_s / fmax(dnv_s, 1.0));
        out[5] = (float)(dco_b / fmax(dnv_b, 1.0));
        out[6] = ps;
        out[7] = pb;
        out[8] = pn;
    }
}

// ---------------------------------------------------------------------------
extern "C" void kernel_launch(void* const* d_in, const int* in_sizes, int n_in,
                              void* d_out, int out_size) {
    const float* sys_logits = (const float*)d_in[0];
    const int*   sys_counts = (const int*)d_in[1];
    const float* bar_logits = (const float*)d_in[2];
    const int*   bar_counts = (const int*)d_in[3];
    const float* notep      = (const float*)d_in[4];
    const int*   gt_sys     = (const int*)d_in[5];
    const int*   gt_bar     = (const int*)d_in[6];
    const float* gtnote     = (const float*)d_in[7];
    const int*   valid      = (const int*)d_in[8];
    const float* lvs        = (const float*)d_in[9];
    const float* lvb        = (const float*)d_in[10];
    const float* lvn        = (const float*)d_in[11];

    int Bn = in_sizes[1];
    if (Bn > MAXB) Bn = MAXB;

    int note_ctas = (Bn + NOTE_CHUNK - 1) / NOTE_CHUNK;
    int target = 148 * 3;                       // one wave at 3 CTAs/SM
    int nce = target - 2 - note_ctas;
    if (nce < 1) nce = 1;
    if (nce > MAXCTA) nce = MAXCTA;
    int grid = 2 + note_ctas + nce;

    fused_kernel<<<grid, 256>>>(
        sys_logits, bar_logits, sys_counts, bar_counts, gt_sys, gt_bar, valid,
        notep, gtnote, lvs, lvb, lvn, Bn, note_ctas, nce, (float*)d_out);
}

// round 7
// speedup vs baseline: 3.8414x; 1.0142x over previous
#include <cuda_runtime.h>
#include <math.h>

// ---------------------------------------------------------------------------
// UncertaintyWeightedLoss — persistent fused kernel, cp.async-pipelined:
//   CTA 0,1        : int4 prefix scan of counts -> g_off, release flag
//   CTA [2,2+NB)   : note-MSE partials
//   CTA [2+NB,..)  : persistent CE warps; per-warp 2-stage SMEM ring filled by
//                    cp.async.cg (16B), compute reads ready stage via LDS.128
//                    into one 20-reg buffer. Warp-shfl softmax-CE + argmax.
//   last CTA       : reduce per-CTA partials, 9 outputs, reset state.
// ---------------------------------------------------------------------------

#define MAXB 16384
#define K4   5                    // float4/lane -> capacity 640 elems
#define BUFE 640                  // floats per smem stage
#define NWARP 8
#define NOTE_CHUNK 256
#define MAXCTA 1024
#define L2E 1.4426950408889634f

__device__ int           g_off[2][MAXB];
__device__ double        g_part_ce_s[MAXCTA];
__device__ double        g_part_ce_b[MAXCTA];
__device__ unsigned int  g_part_cnt[MAXCTA];
__device__ double        g_note_sq[(MAXB + NOTE_CHUNK - 1) / NOTE_CHUNK];
__device__ double        g_note_ns[(MAXB + NOTE_CHUNK - 1) / NOTE_CHUNK];
__device__ unsigned int  g_done;
__device__ unsigned int  g_scan_done;

__device__ __forceinline__ float ex2f(float x) {
    float r;
    asm("ex2.approx.f32 %0, %1;" : "=f"(r) : "f"(x));
    return r;
}
__device__ __forceinline__ unsigned int ldacq(const unsigned int* p) {
    unsigned int v;
    asm volatile("ld.acquire.gpu.u32 %0, [%1];" : "=r"(v) : "l"(p) : "memory");
    return v;
}
__device__ __forceinline__ void cpasync16(unsigned int saddr, const void* gaddr) {
    asm volatile("cp.async.cg.shared.global [%0], [%1], 16;"
                 :: "r"(saddr), "l"(gaddr));
}
__device__ __forceinline__ void cpcommit() {
    asm volatile("cp.async.commit_group;");
}
__device__ __forceinline__ void cpwait1() {
    asm volatile("cp.async.wait_group 1;");
}
__device__ __forceinline__ float wmax(float v) {
    #pragma unroll
    for (int o = 16; o; o >>= 1) v = fmaxf(v, __shfl_xor_sync(0xffffffffu, v, o));
    return v;
}
__device__ __forceinline__ float wsum(float v) {
    #pragma unroll
    for (int o = 16; o; o >>= 1) v += __shfl_xor_sync(0xffffffffu, v, o);
    return v;
}
__device__ __forceinline__ int wmin(int v) {
    #pragma unroll
    for (int o = 16; o; o >>= 1) v = min(v, __shfl_xor_sync(0xffffffffu, v, o));
    return v;
}
__device__ __forceinline__ double blk_sum256(double v, double* s) {
    int t = threadIdx.x;
    s[t] = v;
    __syncthreads();
    #pragma unroll
    for (int k = 128; k > 0; k >>= 1) {
        if (t < k) s[t] += s[t + k];
        __syncthreads();
    }
    double r = s[0];
    __syncthreads();
    return r;
}

// prefix scan for one task, 256 threads, int4-vectorized
__device__ void do_scan(const int* __restrict__ counts, int* __restrict__ offs,
                        int Bn, int* wtot) {
    int t = threadIdx.x, lane = t & 31, wid = t >> 5;
    int CH = (Bn + 255) >> 8;
    int base = t * CH;
    bool vec = ((CH & 3) == 0) && (base + CH <= Bn);

    int sum = 0;
    if (vec) {
        const int4* p = (const int4*)(counts + base);
        int q4 = CH >> 2;
        #pragma unroll 4
        for (int q = 0; q < q4; ++q) {
            int4 v = p[q];
            sum += (v.x + v.y) + (v.z + v.w);
        }
    } else {
        for (int k = 0; k < CH; ++k) {
            int idx = base + k;
            if (idx < Bn) sum += counts[idx];
        }
    }
    int incl = sum;
    #pragma unroll
    for (int o = 1; o < 32; o <<= 1) {
        int v = __shfl_up_sync(0xffffffffu, incl, o);
        if (lane >= o) incl += v;
    }
    if (lane == 31) wtot[wid] = incl;
    __syncthreads();
    if (wid == 0 && lane < 8) {
        int v = wtot[lane];
        #pragma unroll
        for (int o = 1; o < 8; o <<= 1) {
            int u = __shfl_up_sync(0x000000ffu, v, o);
            if (lane >= o) v += u;
        }
        wtot[lane] = v;
    }
    __syncthreads();
    int wbase = (wid == 0) ? 0 : wtot[wid - 1];
    int run = wbase + incl - sum;
    if (vec) {
        const int4* p = (const int4*)(counts + base);
        int4* po = (int4*)(offs + base);
        int q4 = CH >> 2;
        #pragma unroll 4
        for (int q = 0; q < q4; ++q) {
            int4 v = p[q];
            int4 o;
            o.x = run; run += v.x;
            o.y = run; run += v.y;
            o.z = run; run += v.z;
            o.w = run; run += v.w;
            po[q] = o;
        }
    } else {
        for (int k = 0; k < CH; ++k) {
            int idx = base + k;
            if (idx < Bn) { offs[idx] = run; run += counts[idx]; }
        }
    }
}

__global__ __launch_bounds__(256, 4) void fused_kernel(
    const float* __restrict__ sys_logits, const float* __restrict__ bar_logits,
    const int* __restrict__ sys_counts,   const int* __restrict__ bar_counts,
    const int* __restrict__ gt_sys,       const int* __restrict__ gt_bar,
    const int* __restrict__ valid,
    const float* __restrict__ notep,      const float* __restrict__ gtnote,
    const float* __restrict__ lv_sys,     const float* __restrict__ lv_bar,
    const float* __restrict__ lv_note,
    int Bn, int note_ctas, int nce, float* __restrict__ out) {

    __shared__ float  ring[NWARP][2][BUFE];       // 40 KB cp.async staging
    __shared__ double sbuf[256];
    __shared__ int    wtot[8];
    __shared__ float  s_ce[2][8];
    __shared__ int    s_nv[2][8], s_co[2][8];
    __shared__ unsigned int ticket;

    int cta = blockIdx.x;
    int t = threadIdx.x;
    const float NEGINF = __int_as_float(0xff800000);
    int ce_base = 2 + note_ctas;

    if (cta < 2) {
        do_scan(cta == 0 ? sys_counts : bar_counts, g_off[cta], Bn, wtot);
        __threadfence();
        __syncthreads();
        if (t == 0) atomicAdd(&g_scan_done, 1u);
    } else if (cta < ce_base) {
        int nb = cta - 2;
        int i = nb * NOTE_CHUNK + t;
        double sq = 0.0, ns = 0.0;
        if (i < Bn && valid[i] != 0) {
            double d = (double)notep[i] - (double)gtnote[i];
            sq = d * d;
            ns = 1.0;
        }
        sq = blk_sum256(sq, sbuf);
        ns = blk_sum256(ns, sbuf);
        if (t == 0) { g_note_sq[nb] = sq; g_note_ns[nb] = ns; }
    } else {
        // ---------------- persistent cp.async-pipelined CE ----------------
        int lane = t & 31;
        int w = t >> 5;
        int tot = 2 * Bn;
        int stride = nce << 3;
        int gw = ((cta - ce_base) << 3) | w;

        if (t == 0) {
            while (ldacq(&g_scan_done) < 2u) __nanosleep(64);
        }
        __syncthreads();

        float ces = 0.0f, ceb = 0.0f;
        int nvs = 0, cos_ = 0, nvb = 0, cob = 0;

        unsigned int shb[2];
        shb[0] = (unsigned int)__cvta_generic_to_shared(&ring[w][0][0]);
        shb[1] = (unsigned int)__cvta_generic_to_shared(&ring[w][1][0]);

        auto fetchmeta = [&](int s, int& c, int& o, int& g, int& v) {
            if (s < tot) {
                int task = (s >= Bn) ? 1 : 0;
                int b = s - task * Bn;
                c = task ? bar_counts[b] : sys_counts[b];
                o = __ldcg(&g_off[task][b]);
                g = task ? gt_bar[b] : gt_sys[b];
                v = valid[b];
            } else { c = 0; o = 0; g = 0; v = 0; }
        };
        // issue cp.async for one segment into stage p (fast path only)
        auto issue = [&](int p, int s, int c, int o) {
            if (s < tot && ((o | c) & 3) == 0 && c <= BUFE) {
                const float* ptr = (s >= Bn) ? bar_logits : sys_logits;
                const float4* src = (const float4*)(ptr + o);
                int c4 = c >> 2;
                unsigned int base = shb[p];
                #pragma unroll
                for (int k = 0; k < K4; ++k) {
                    int vi = lane + (k << 5);
                    if (vi < c4) cpasync16(base + vi * 16, src + vi);
                }
            }
            cpcommit();
        };
        auto process = [&](int p, int s, int c, int o, int g, int vld) {
            if (s >= tot) return;
            int task = (s >= Bn) ? 1 : 0;
            float m, Z, tlogit;
            int arg;
            if (((o | c) & 3) == 0 && c <= BUFE) {
                // load ready stage smem -> regs
                const float4* sb = (const float4*)&ring[w][p][0];
                int c4 = c >> 2;
                float4 x[K4];
                #pragma unroll
                for (int k = 0; k < K4; ++k) {
                    int vi = lane + (k << 5);
                    if (vi < c4) x[k] = sb[vi];
                    else x[k] = make_float4(NEGINF, NEGINF, NEGINF, NEGINF);
                }
                float mymax = NEGINF;
                #pragma unroll
                for (int k = 0; k < K4; ++k)
                    mymax = fmaxf(fmaxf(fmaxf(mymax, x[k].x),
                                        fmaxf(x[k].y, x[k].z)), x[k].w);
                m = wmax(mymax);
                float a = m * L2E;
                float sm = 0.0f;
                int myarg = 0x7fffffff;
                #pragma unroll
                for (int k = 0; k < K4; ++k) {
                    int e = (lane + (k << 5)) << 2;
                    sm += ex2f(fmaf(x[k].x, L2E, -a))
                        + ex2f(fmaf(x[k].y, L2E, -a))
                        + ex2f(fmaf(x[k].z, L2E, -a))
                        + ex2f(fmaf(x[k].w, L2E, -a));
                    if (x[k].x == m) myarg = min(myarg, e + 0);
                    if (x[k].y == m) myarg = min(myarg, e + 1);
                    if (x[k].z == m) myarg = min(myarg, e + 2);
                    if (x[k].w == m) myarg = min(myarg, e + 3);
                }
                Z = wsum(sm);
                arg = wmin(myarg);
                // target logit from smem (cheap, L1/smem hit)
                int gi = min(max(g, 0), c > 0 ? c - 1 : 0);
                tlogit = ring[w][p][gi];
            } else {
                const float* ptr = task ? bar_logits : sys_logits;
                float mymax = NEGINF;
                for (int i = lane; i < c; i += 32)
                    mymax = fmaxf(mymax, ptr[o + i]);
                m = wmax(mymax);
                float a = m * L2E;
                float sm = 0.0f;
                int myarg = 0x7fffffff;
                for (int i = lane; i < c; i += 32) {
                    float v = ptr[o + i];
                    sm += ex2f(fmaf(v, L2E, -a));
                    if (v == m) myarg = min(myarg, i);
                }
                Z = wsum(sm);
                arg = wmin(myarg);
                tlogit = (g >= 0 && g < c) ? ptr[o + g] : 0.0f;
            }
            if (lane == 0) {
                bool vmask = (c > 0) && (g >= 0) && (g < c) && (vld != 0);
                if (vmask) {
                    float ce = logf(Z) + m - tlogit;
                    int cor = (arg == g) ? 1 : 0;
                    if (task) { ceb += ce; nvb += 1; cob += cor; }
                    else      { ces += ce; nvs += 1; cos_ += cor; }
                }
            }
        };

        // software pipeline, depth 2
        int s0 = gw, s1 = gw + stride;
        int c0, o0, g0, v0, c1, o1, g1, v1;
        fetchmeta(s0, c0, o0, g0, v0);
        fetchmeta(s1, c1, o1, g1, v1);
        issue(0, s0, c0, o0);
        issue(1, s1, c1, o1);
        int p = 0;
        while (s0 < tot) {
            int s2 = s1 + stride;
            int c2, o2, g2, v2;
            fetchmeta(s2, c2, o2, g2, v2);
            cpwait1();                       // stage p complete
            process(p, s0, c0, o0, g0, v0);
            issue(p, s2, c2, o2);            // reuse stage p for s+2
            s0 = s1; c0 = c1; o0 = o1; g0 = g1; v0 = v1;
            s1 = s2; c1 = c2; o1 = o2; g1 = g2; v1 = v2;
            p ^= 1;
        }

        if (lane == 0) {
            s_ce[0][w] = ces; s_ce[1][w] = ceb;
            s_nv[0][w] = nvs; s_nv[1][w] = nvb;
            s_co[0][w] = cos_; s_co[1][w] = cob;
        }
        __syncthreads();
        if (t == 0) {
            float tce_s = 0.0f, tce_b = 0.0f;
            int tnv_s = 0, tco_s = 0, tnv_b = 0, tco_b = 0;
            #pragma unroll
            for (int i = 0; i < 8; ++i) {
                tce_s += s_ce[0][i]; tce_b += s_ce[1][i];
                tnv_s += s_nv[0][i]; tnv_b += s_nv[1][i];
                tco_s += s_co[0][i]; tco_b += s_co[1][i];
            }
            int ci = cta - ce_base;
            g_part_ce_s[ci] = (double)tce_s;
            g_part_ce_b[ci] = (double)tce_b;
            g_part_cnt[ci] = (unsigned int)tnv_s | ((unsigned int)tco_s << 8)
                           | ((unsigned int)tnv_b << 16) | ((unsigned int)tco_b << 24);
        }
    }

    // ---------------- ticket + last-CTA finalize ----------------
    __syncthreads();
    __threadfence();
    if (t == 0) ticket = atomicAdd(&g_done, 1u);
    __syncthreads();
    if (ticket != gridDim.x - 1) return;

    if (t == 0) { g_done = 0; g_scan_done = 0; }

    double ce_s = 0, ce_b = 0, sq = 0, ns = 0;
    int nv_s = 0, co_s = 0, nv_b = 0, co_b = 0;

    for (int i = t; i < nce; i += 256) {
        ce_s += __ldcg(&g_part_ce_s[i]);
        ce_b += __ldcg(&g_part_ce_b[i]);
        unsigned int pc = __ldcg(&g_part_cnt[i]);
        nv_s += pc & 0xff;         co_s += (pc >> 8) & 0xff;
        nv_b += (pc >> 16) & 0xff; co_b += (pc >> 24) & 0xff;
    }
    for (int i = t; i < note_ctas; i += 256) {
        sq += __ldcg(&g_note_sq[i]);
        ns += __ldcg(&g_note_ns[i]);
    }

    ce_s = blk_sum256(ce_s, sbuf);
    double dnv_s = blk_sum256((double)nv_s, sbuf);
    double dco_s = blk_sum256((double)co_s, sbuf);
    ce_b = blk_sum256(ce_b, sbuf);
    double dnv_b = blk_sum256((double)nv_b, sbuf);
    double dco_b = blk_sum256((double)co_b, sbuf);
    sq = blk_sum256(sq, sbuf);
    ns = blk_sum256(ns, sbuf);

    if (t == 0) {
        double sys_loss  = ce_s / fmax(dnv_s, 1.0);
        double bar_loss  = ce_b / fmax(dnv_b, 1.0);
        double note_loss = (ns > 0.0) ? sq / fmax(ns, 1.0) : 0.0;

        float lvs = lv_sys[0], lvb = lv_bar[0], lvn = lv_note[0];
        float ps = expf(-lvs), pb = expf(-lvb), pn = expf(-lvn);

        double loss = 0.5 * (double)ps * sys_loss + 0.5 * (double)lvs
                    + 0.5 * (double)pb * bar_loss + 0.5 * (double)lvb
                    + 0.5 * (double)pn * note_loss + 0.5 * (double)lvn;

        out[0] = (float)loss;
        out[1] = (float)sys_loss;
        out[2] = (float)bar_loss;
        out[3] = (float)note_loss;
        out[4] = (float)(dco_s / fmax(dnv_s, 1.0));
        out[5] = (float)(dco_b / fmax(dnv_b, 1.0));
        out[6] = ps;
        out[7] = pb;
        out[8] = pn;
    }
}

// ---------------------------------------------------------------------------
extern "C" void kernel_launch(void* const* d_in, const int* in_sizes, int n_in,
                              void* d_out, int out_size) {
    const float* sys_logits = (const float*)d_in[0];
    const int*   sys_counts = (const int*)d_in[1];
    const float* bar_logits = (const float*)d_in[2];
    const int*   bar_counts = (const int*)d_in[3];
    const float* notep      = (const float*)d_in[4];
    const int*   gt_sys     = (const int*)d_in[5];
    const int*   gt_bar     = (const int*)d_in[6];
    const float* gtnote     = (const float*)d_in[7];
    const int*   valid      = (const int*)d_in[8];
    const float* lvs        = (const float*)d_in[9];
    const float* lvb        = (const float*)d_in[10];
    const float* lvn        = (const float*)d_in[11];

    int Bn = in_sizes[1];
    if (Bn > MAXB) Bn = MAXB;

    int note_ctas = (Bn + NOTE_CHUNK - 1) / NOTE_CHUNK;
    int target = 148 * 4;                  // one wave at 4 CTAs/SM
    int nce = target - 2 - note_ctas;
    if (nce < 1) nce = 1;
    if (nce > MAXCTA) nce = MAXCTA;
    int grid = 2 + note_ctas + nce;

    fused_kernel<<<grid, 256>>>(
        sys_logits, bar_logits, sys_counts, bar_counts, gt_sys, gt_bar, valid,
        notep, gtnote, lvs, lvb, lvn, Bn, note_ctas, nce, (float*)d_out);
}

// round 8
// speedup vs baseline: 4.4026x; 1.1461x over previous
#include <cuda_runtime.h>
#include <math.h>

// ---------------------------------------------------------------------------
// UncertaintyWeightedLoss — persistent fused kernel, cp.async-pipelined.
//   CTA 0,1        : int4 prefix scan of counts -> g_off, release flag
//   CTA [2,2+NB)   : note-MSE partials
//   CTA [2+NB,..)  : persistent CE warps. Prologue: one lane per future round
//                    loads that segment's meta (4 coalesced LDGs total);
//                    rounds get meta via shfl. 2-stage per-warp smem ring via
//                    cp.async.cg. Fast path: max + sum-exp only (4 ops/elem);
//                    first-occurrence argmax computed ONLY when the target
//                    logit equals the max (rare, warp-uniform, exact).
//   last CTA       : reduce per-CTA partials, 9 outputs, reset state.
// ---------------------------------------------------------------------------

#define MAXB 16384
#define K4   5                    // float4/lane -> capacity 640 elems
#define BUFE 640                  // floats per smem stage
#define NWARP 8
#define NOTE_CHUNK 256
#define MAXCTA 1024
#define L2E 1.4426950408889634f

__device__ int           g_off[2][MAXB];
__device__ double        g_part_ce_s[MAXCTA];
__device__ double        g_part_ce_b[MAXCTA];
__device__ uint2         g_part_cnt[MAXCTA];   // x: nv_s|co_s<<16, y: nv_b|co_b<<16
__device__ double        g_note_sq[(MAXB + NOTE_CHUNK - 1) / NOTE_CHUNK];
__device__ double        g_note_ns[(MAXB + NOTE_CHUNK - 1) / NOTE_CHUNK];
__device__ unsigned int  g_done;
__device__ unsigned int  g_scan_done;

__device__ __forceinline__ float ex2f(float x) {
    float r;
    asm("ex2.approx.f32 %0, %1;" : "=f"(r) : "f"(x));
    return r;
}
__device__ __forceinline__ unsigned int ldacq(const unsigned int* p) {
    unsigned int v;
    asm volatile("ld.acquire.gpu.u32 %0, [%1];" : "=r"(v) : "l"(p) : "memory");
    return v;
}
__device__ __forceinline__ void cpasync16(unsigned int saddr, const void* gaddr) {
    asm volatile("cp.async.cg.shared.global [%0], [%1], 16;"
                 :: "r"(saddr), "l"(gaddr));
}
__device__ __forceinline__ void cpcommit() {
    asm volatile("cp.async.commit_group;");
}
__device__ __forceinline__ void cpwait1() {
    asm volatile("cp.async.wait_group 1;");
}
__device__ __forceinline__ float wmax(float v) {
    #pragma unroll
    for (int o = 16; o; o >>= 1) v = fmaxf(v, __shfl_xor_sync(0xffffffffu, v, o));
    return v;
}
__device__ __forceinline__ float wsum(float v) {
    #pragma unroll
    for (int o = 16; o; o >>= 1) v += __shfl_xor_sync(0xffffffffu, v, o);
    return v;
}
__device__ __forceinline__ int wmin(int v) {
    #pragma unroll
    for (int o = 16; o; o >>= 1) v = min(v, __shfl_xor_sync(0xffffffffu, v, o));
    return v;
}
__device__ __forceinline__ double blk_sum256(double v, double* s) {
    int t = threadIdx.x;
    s[t] = v;
    __syncthreads();
    #pragma unroll
    for (int k = 128; k > 0; k >>= 1) {
        if (t < k) s[t] += s[t + k];
        __syncthreads();
    }
    double r = s[0];
    __syncthreads();
    return r;
}

// prefix scan for one task, 256 threads, int4-vectorized
__device__ void do_scan(const int* __restrict__ counts, int* __restrict__ offs,
                        int Bn, int* wtot) {
    int t = threadIdx.x, lane = t & 31, wid = t >> 5;
    int CH = (Bn + 255) >> 8;
    int base = t * CH;
    bool vec = ((CH & 3) == 0) && (base + CH <= Bn);

    int sum = 0;
    if (vec) {
        const int4* p = (const int4*)(counts + base);
        int q4 = CH >> 2;
        #pragma unroll 4
        for (int q = 0; q < q4; ++q) {
            int4 v = p[q];
            sum += (v.x + v.y) + (v.z + v.w);
        }
    } else {
        for (int k = 0; k < CH; ++k) {
            int idx = base + k;
            if (idx < Bn) sum += counts[idx];
        }
    }
    int incl = sum;
    #pragma unroll
    for (int o = 1; o < 32; o <<= 1) {
        int v = __shfl_up_sync(0xffffffffu, incl, o);
        if (lane >= o) incl += v;
    }
    if (lane == 31) wtot[wid] = incl;
    __syncthreads();
    if (wid == 0 && lane < 8) {
        int v = wtot[lane];
        #pragma unroll
        for (int o = 1; o < 8; o <<= 1) {
            int u = __shfl_up_sync(0x000000ffu, v, o);
            if (lane >= o) v += u;
        }
        wtot[lane] = v;
    }
    __syncthreads();
    int wbase = (wid == 0) ? 0 : wtot[wid - 1];
    int run = wbase + incl - sum;
    if (vec) {
        const int4* p = (const int4*)(counts + base);
        int4* po = (int4*)(offs + base);
        int q4 = CH >> 2;
        #pragma unroll 4
        for (int q = 0; q < q4; ++q) {
            int4 v = p[q];
            int4 o;
            o.x = run; run += v.x;
            o.y = run; run += v.y;
            o.z = run; run += v.z;
            o.w = run; run += v.w;
            po[q] = o;
        }
    } else {
        for (int k = 0; k < CH; ++k) {
            int idx = base + k;
            if (idx < Bn) { offs[idx] = run; run += counts[idx]; }
        }
    }
}

__global__ __launch_bounds__(256, 4) void fused_kernel(
    const float* __restrict__ sys_logits, const float* __restrict__ bar_logits,
    const int* __restrict__ sys_counts,   const int* __restrict__ bar_counts,
    const int* __restrict__ gt_sys,       const int* __restrict__ gt_bar,
    const int* __restrict__ valid,
    const float* __restrict__ notep,      const float* __restrict__ gtnote,
    const float* __restrict__ lv_sys,     const float* __restrict__ lv_bar,
    const float* __restrict__ lv_note,
    int Bn, int note_ctas, int nce, float* __restrict__ out) {

    __shared__ float  ring[NWARP][2][BUFE];       // 40 KB cp.async staging
    __shared__ double sbuf[256];
    __shared__ int    wtot[8];
    __shared__ float  s_ce[2][8];
    __shared__ int    s_nv[2][8], s_co[2][8];
    __shared__ unsigned int ticket;

    int cta = blockIdx.x;
    int t = threadIdx.x;
    const float NEGINF = __int_as_float(0xff800000);
    int ce_base = 2 + note_ctas;

    if (cta < 2) {
        do_scan(cta == 0 ? sys_counts : bar_counts, g_off[cta], Bn, wtot);
        __threadfence();
        __syncthreads();
        if (t == 0) atomicAdd(&g_scan_done, 1u);
    } else if (cta < ce_base) {
        int nb = cta - 2;
        int i = nb * NOTE_CHUNK + t;
        double sq = 0.0, ns = 0.0;
        if (i < Bn && valid[i] != 0) {
            double d = (double)notep[i] - (double)gtnote[i];
            sq = d * d;
            ns = 1.0;
        }
        sq = blk_sum256(sq, sbuf);
        ns = blk_sum256(ns, sbuf);
        if (t == 0) { g_note_sq[nb] = sq; g_note_ns[nb] = ns; }
    } else {
        // ---------------- persistent cp.async-pipelined CE ----------------
        int lane = t & 31;
        int w = t >> 5;
        int tot = 2 * Bn;
        int stride = nce << 3;
        int gw = ((cta - ce_base) << 3) | w;

        float ces = 0.0f, ceb = 0.0f;
        int nvs = 0, cos_ = 0, nvb = 0, cob = 0;

        unsigned int shb[2];
        shb[0] = (unsigned int)__cvta_generic_to_shared(&ring[w][0][0]);
        shb[1] = (unsigned int)__cvta_generic_to_shared(&ring[w][1][0]);

        // ---- prologue: per-lane meta for this warp's future rounds ----
        // lane r handles round r's segment: 4 coalesced-ish LDGs for ALL rounds
        int msl = gw + lane * stride;                 // lane r's segment id
        int mtask = (msl >= Bn) ? 1 : 0;
        int mb = msl - mtask * Bn;
        int mc = 0, mg = 0, mv = 0, mo = 0;
        bool mok = (msl < tot);
        if (mok) {
            mc = mtask ? bar_counts[mb] : sys_counts[mb];
            mg = mtask ? gt_bar[mb] : gt_sys[mb];
            mv = valid[mb];
        }
        // offsets need the scan -> spin, then load
        if (t == 0) {
            while (ldacq(&g_scan_done) < 2u) __nanosleep(64);
        }
        __syncthreads();
        if (mok) mo = __ldcg(&g_off[mtask][mb]);

        auto getmeta = [&](int r, int& c, int& o, int& g, int& v) {
            c = __shfl_sync(0xffffffffu, mc, r);
            o = __shfl_sync(0xffffffffu, mo, r);
            g = __shfl_sync(0xffffffffu, mg, r);
            v = __shfl_sync(0xffffffffu, mv, r);
        };
        auto issue = [&](int p, int s, int c, int o) {
            if (s < tot && ((o | c) & 3) == 0 && c <= BUFE) {
                const float* ptr = (s >= Bn) ? bar_logits : sys_logits;
                const float4* src = (const float4*)(ptr + o);
                int c4 = c >> 2;
                unsigned int base = shb[p];
                #pragma unroll
                for (int k = 0; k < K4; ++k) {
                    int vi = lane + (k << 5);
                    if (vi < c4) cpasync16(base + vi * 16, src + vi);
                }
            }
            cpcommit();
        };
        auto process = [&](int p, int s, int c, int o, int g, int vld) {
            if (s >= tot) return;
            int task = (s >= Bn) ? 1 : 0;
            float m, Z, tlogit;
            bool cor;
            if (((o | c) & 3) == 0 && c <= BUFE) {
                const float4* sb = (const float4*)&ring[w][p][0];
                int c4 = c >> 2;
                float4 x[K4];
                #pragma unroll
                for (int k = 0; k < K4; ++k) {
                    int vi = lane + (k << 5);
                    if (vi < c4) x[k] = sb[vi];
                    else x[k] = make_float4(NEGINF, NEGINF, NEGINF, NEGINF);
                }
                float mymax = NEGINF;
                #pragma unroll
                for (int k = 0; k < K4; ++k)
                    mymax = fmaxf(fmaxf(fmaxf(mymax, x[k].x),
                                        fmaxf(x[k].y, x[k].z)), x[k].w);
                m = wmax(mymax);
                float a = m * L2E;
                float sm = 0.0f;
                #pragma unroll
                for (int k = 0; k < K4; ++k) {
                    sm += ex2f(fmaf(x[k].x, L2E, -a))
                        + ex2f(fmaf(x[k].y, L2E, -a))
                        + ex2f(fmaf(x[k].z, L2E, -a))
                        + ex2f(fmaf(x[k].w, L2E, -a));
                }
                Z = wsum(sm);
                // uniform smem load (broadcast) of the target logit
                int gi = min(max(g, 0), c > 0 ? c - 1 : 0);
                tlogit = ring[w][p][gi];
                // first-occurrence argmax ONLY if target could be the max
                cor = false;
                if (tlogit == m) {                 // warp-uniform, rare
                    int myarg = 0x7fffffff;
                    #pragma unroll
                    for (int k = 0; k < K4; ++k) {
                        int e = (lane + (k << 5)) << 2;
                        if (x[k].x == m) myarg = min(myarg, e + 0);
                        if (x[k].y == m) myarg = min(myarg, e + 1);
                        if (x[k].z == m) myarg = min(myarg, e + 2);
                        if (x[k].w == m) myarg = min(myarg, e + 3);
                    }
                    cor = (wmin(myarg) == g);
                }
            } else {
                // streaming fallback for oversized segments
                const float* ptr = task ? bar_logits : sys_logits;
                float mymax = NEGINF;
                for (int i = lane; i < c; i += 32)
                    mymax = fmaxf(mymax, ptr[o + i]);
                m = wmax(mymax);
                float a = m * L2E;
                float sm = 0.0f;
                int myarg = 0x7fffffff;
                for (int i = lane; i < c; i += 32) {
                    float v = ptr[o + i];
                    sm += ex2f(fmaf(v, L2E, -a));
                    if (v == m) myarg = min(myarg, i);
                }
                Z = wsum(sm);
                int arg = wmin(myarg);
                tlogit = (g >= 0 && g < c) ? ptr[o + g] : 0.0f;
                cor = (arg == g);
            }
            if (lane == 0) {
                bool vmask = (c > 0) && (g >= 0) && (g < c) && (vld != 0);
                if (vmask) {
                    float ce = logf(Z) + m - tlogit;
                    int ci = cor ? 1 : 0;
                    if (task) { ceb += ce; nvb += 1; cob += ci; }
                    else      { ces += ce; nvs += 1; cos_ += ci; }
                }
            }
        };

        // software pipeline, depth 2 (meta via shfl — no LDG in steady loop)
        int s0 = gw, s1 = gw + stride;
        int c0, o0, g0, v0, c1, o1, g1, v1;
        getmeta(0, c0, o0, g0, v0);
        getmeta(1, c1, o1, g1, v1);
        issue(0, s0, c0, o0);
        issue(1, s1, c1, o1);
        int p = 0, r = 2;
        while (s0 < tot) {
            int s2 = s1 + stride;
            int c2, o2, g2, v2;
            getmeta(min(r, 31), c2, o2, g2, v2);
            cpwait1();                        // stage p ready
            process(p, s0, c0, o0, g0, v0);
            issue(p, s2, c2, o2);             // stage p reused for round r
            s0 = s1; c0 = c1; o0 = o1; g0 = g1; v0 = v1;
            s1 = s2; c1 = c2; o1 = o2; g1 = g2; v1 = v2;
            p ^= 1;
            ++r;
        }

        if (lane == 0) {
            s_ce[0][w] = ces; s_ce[1][w] = ceb;
            s_nv[0][w] = nvs; s_nv[1][w] = nvb;
            s_co[0][w] = cos_; s_co[1][w] = cob;
        }
        __syncthreads();
        if (t == 0) {
            float tce_s = 0.0f, tce_b = 0.0f;
            int tnv_s = 0, tco_s = 0, tnv_b = 0, tco_b = 0;
            #pragma unroll
            for (int i = 0; i < 8; ++i) {
                tce_s += s_ce[0][i]; tce_b += s_ce[1][i];
                tnv_s += s_nv[0][i]; tnv_b += s_nv[1][i];
                tco_s += s_co[0][i]; tco_b += s_co[1][i];
            }
            int ci = cta - ce_base;
            g_part_ce_s[ci] = (double)tce_s;
            g_part_ce_b[ci] = (double)tce_b;
            g_part_cnt[ci] = make_uint2(
                (unsigned int)tnv_s | ((unsigned int)tco_s << 16),
                (unsigned int)tnv_b | ((unsigned int)tco_b << 16));
        }
    }

    // ---------------- ticket + last-CTA finalize ----------------
    __syncthreads();
    __threadfence();
    if (t == 0) ticket = atomicAdd(&g_done, 1u);
    __syncthreads();
    if (ticket != gridDim.x - 1) return;

    if (t == 0) { g_done = 0; g_scan_done = 0; }

    double ce_s = 0, ce_b = 0, sq = 0, ns = 0;
    int nv_s = 0, co_s = 0, nv_b = 0, co_b = 0;

    for (int i = t; i < nce; i += 256) {
        ce_s += __ldcg(&g_part_ce_s[i]);
        ce_b += __ldcg(&g_part_ce_b[i]);
        uint2 pc = __ldcg(&g_part_cnt[i]);
        nv_s += pc.x & 0xffff; co_s += pc.x >> 16;
        nv_b += pc.y & 0xffff; co_b += pc.y >> 16;
    }
    for (int i = t; i < note_ctas; i += 256) {
        sq += __ldcg(&g_note_sq[i]);
        ns += __ldcg(&g_note_ns[i]);
    }

    ce_s = blk_sum256(ce_s, sbuf);
    double dnv_s = blk_sum256((double)nv_s, sbuf);
    double dco_s = blk_sum256((double)co_s, sbuf);
    ce_b = blk_sum256(ce_b, sbuf);
    double dnv_b = blk_sum256((double)nv_b, sbuf);
    double dco_b = blk_sum256((double)co_b, sbuf);
    sq = blk_sum256(sq, sbuf);
    ns = blk_sum256(ns, sbuf);

    if (t == 0) {
        double sys_loss  = ce_s / fmax(dnv_s, 1.0);
        double bar_loss  = ce_b / fmax(dnv_b, 1.0);
        double note_loss = (ns > 0.0) ? sq / fmax(ns, 1.0) : 0.0;

        float lvs = lv_sys[0], lvb = lv_bar[0], lvn = lv_note[0];
        float ps = expf(-lvs), pb = expf(-lvb), pn = expf(-lvn);

        double loss = 0.5 * (double)ps * sys_loss + 0.5 * (double)lvs
                    + 0.5 * (double)pb * bar_loss + 0.5 * (double)lvb
                    + 0.5 * (double)pn * note_loss + 0.5 * (double)lvn;

        out[0] = (float)loss;
        out[1] = (float)sys_loss;
        out[2] = (float)bar_loss;
        out[3] = (float)note_loss;
        out[4] = (float)(dco_s / fmax(dnv_s, 1.0));
        out[5] = (float)(dco_b / fmax(dnv_b, 1.0));
        out[6] = ps;
        out[7] = pb;
        out[8] = pn;
    }
}

// ---------------------------------------------------------------------------
extern "C" void kernel_launch(void* const* d_in, const int* in_sizes, int n_in,
                              void* d_out, int out_size) {
    const float* sys_logits = (const float*)d_in[0];
    const int*   sys_counts = (const int*)d_in[1];
    const float* bar_logits = (const float*)d_in[2];
    const int*   bar_counts = (const int*)d_in[3];
    const float* notep      = (const float*)d_in[4];
    const int*   gt_sys     = (const int*)d_in[5];
    const int*   gt_bar     = (const int*)d_in[6];
    const float* gtnote     = (const float*)d_in[7];
    const int*   valid      = (const int*)d_in[8];
    const float* lvs        = (const float*)d_in[9];
    const float* lvb        = (const float*)d_in[10];
    const float* lvn        = (const float*)d_in[11];

    int Bn = in_sizes[1];
    if (Bn > MAXB) Bn = MAXB;

    int note_ctas = (Bn + NOTE_CHUNK - 1) / NOTE_CHUNK;
    int target = 148 * 4;                  // one wave at 4 CTAs/SM
    int nce = target - 2 - note_ctas;
    if (nce < 1) nce = 1;
    if (nce > MAXCTA) nce = MAXCTA;
    // keep per-warp rounds <= 32 (meta lanes); tot/stride <= 32
    int grid = 2 + note_ctas + nce;

    fused_kernel<<<grid, 256>>>(
        sys_logits, bar_logits, sys_counts, bar_counts, gt_sys, gt_bar, valid,
        notep, gtnote, lvs, lvb, lvn, Bn, note_ctas, nce, (float*)d_out);
}